// round 6
// baseline (speedup 1.0000x reference)
#include <cuda_runtime.h>

typedef unsigned long long ull;

// ---------------- f32x2 packed math (FFMA2 — PTX-only on sm_103a) ----------
#define FMA2(d,a,b,c) asm("fma.rn.f32x2 %0, %1, %2, %3;" : "=l"(d) : "l"(a), "l"(b), "l"(c))
#define MUL2(d,a,b)   asm("mul.rn.f32x2 %0, %1, %2;"     : "=l"(d) : "l"(a), "l"(b))
#define ADD2(d,a,b)   asm("add.rn.f32x2 %0, %1, %2;"     : "=l"(d) : "l"(a), "l"(b))
#define EX2(d,s)      asm("ex2.approx.f32 %0, %1;"       : "=f"(d) : "f"(s))

__device__ __forceinline__ ull splat2(float f) {
    unsigned u = __float_as_uint(f);
    return ((ull)u << 32) | (ull)u;
}
__device__ __forceinline__ float lo2(ull v) { return __uint_as_float((unsigned)v); }
__device__ __forceinline__ float hi2(ull v) { return __uint_as_float((unsigned)(v >> 32)); }
__device__ __forceinline__ ull pack2(float lo, float hi) {
    return ((ull)__float_as_uint(hi) << 32) | (ull)__float_as_uint(lo);
}

// ---------------- problem constants ----------------------------------------
// B=2, C=256, N=4096, NUM_HEAD=4, D=8, AT_HEAD=64, BH=8
#define NTOK   4096
#define BH_CNT 8
#define NSPLIT 8                 // n-range splits
#define NSEG   (NTOK / NSPLIT)   // 512 n per attn item
#define MT_CNT 8                 // m-tiles of 512
#define N_ITEMS (BH_CNT * NSPLIT * MT_CNT)   // 512 work items

#define LOG2E  1.4426950408889634f

// ---------------- device scratch (no allocation allowed) -------------------
// Q/V: interleaved pair layout [bh][n/2][d*2 + (n&1)]   (q pre-scaled by log2e)
// K  : [bh][n][d]
__device__ float g_Q[BH_CNT * NTOK * 8];
__device__ float g_K[BH_CNT * NTOK * 8];
__device__ float g_V[BH_CNT * NTOK * 8];
// partials: [bh][split][j in 0..8 (8 num + 1 den)][m]
__device__ float g_P[BH_CNT * NSPLIT * 9 * NTOK];
// dynamic work queue ticket (reset by qkv_kernel each launch)
__device__ unsigned g_ticket;

// ============================================================================
// Kernel 1: fused QKV projection, register-tiled GEMM with f32x2 row-pairs.
// C[96 x 8192] = W[96 x 256] @ X[256 x 8192].
// 128 blocks; block = all 96 rows x 64 n of one b. 256 threads:
//   rg = warp id -> 12 rows (6 row-pairs), ng -> 2 n.
// Per scalar k: 3 broadcast LDS.128 (W row-pairs) + 1 LDS.64 (x) + 12 FFMA2.
// ============================================================================
#define WPAD 100   // W smem row stride (floats): mult of 4, bank-spread

__global__ void __launch_bounds__(256) qkv_kernel(
    const float* __restrict__ x,
    const float* __restrict__ Wq, const float* __restrict__ bq,
    const float* __restrict__ Wk, const float* __restrict__ bk,
    const float* __restrict__ Wv, const float* __restrict__ bv)
{
    __shared__ __align__(16) float xs[64 * 64];     // [k_local][n]  16 KB
    __shared__ __align__(16) float ws[64 * WPAD];   // [k_local][r]  25.6 KB

    if (blockIdx.x == 0 && threadIdx.x == 0) g_ticket = 0;  // reset attn queue

    const int b   = blockIdx.x >> 6;            // 128 blocks: 64 per b
    const int n0  = (blockIdx.x & 63) * 64;
    const int tid = threadIdx.x;
    const int rg  = tid >> 5;                   // 0..7, constant per warp
    const int ng  = tid & 31;                   // 2 n each

    ull acc2[6][2];                              // [row-pair][n]
#pragma unroll
    for (int pr = 0; pr < 6; ++pr) { acc2[pr][0] = 0ull; acc2[pr][1] = 0ull; }

    for (int kc = 0; kc < 4; ++kc) {
        const int kb = kc * 64;
        __syncthreads();
        // stage x chunk: x[b][kb + c][n0..n0+63]  (1024 float4)
#pragma unroll
        for (int t = 0; t < 4; ++t) {
            int idx = tid + t * 256;
            int c   = idx >> 4;
            int nq  = idx & 15;
            float4 xv = __ldg((const float4*)(x + (b * 256 + kb + c) * NTOK + n0) + nq);
            *(float4*)&xs[c * 64 + nq * 4] = xv;
        }
        // stage W chunk: ws[k][r] = W[r][kb + k]
#pragma unroll
        for (int t = 0; t < 6; ++t) {
            int idx = tid + t * 256;
            int r   = idx >> 4;
            int k4  = idx & 15;
            const float* base = (r < 32) ? Wq : ((r < 64) ? Wk : Wv);
            float4 w = __ldg((const float4*)(base + (r & 31) * 256 + kb) + k4);
            ws[(k4 * 4 + 0) * WPAD + r] = w.x;
            ws[(k4 * 4 + 1) * WPAD + r] = w.y;
            ws[(k4 * 4 + 2) * WPAD + r] = w.z;
            ws[(k4 * 4 + 3) * WPAD + r] = w.w;
        }
        __syncthreads();

#pragma unroll 8
        for (int k = 0; k < 64; ++k) {
            float2 xv = *(const float2*)&xs[k * 64 + ng * 2];
            ull x0 = splat2(xv.x);
            ull x1 = splat2(xv.y);
            const ulonglong2* wr = (const ulonglong2*)&ws[k * WPAD + rg * 12];
            ulonglong2 wa = wr[0], wb = wr[1], wc = wr[2];
            FMA2(acc2[0][0], wa.x, x0, acc2[0][0]); FMA2(acc2[0][1], wa.x, x1, acc2[0][1]);
            FMA2(acc2[1][0], wa.y, x0, acc2[1][0]); FMA2(acc2[1][1], wa.y, x1, acc2[1][1]);
            FMA2(acc2[2][0], wb.x, x0, acc2[2][0]); FMA2(acc2[2][1], wb.x, x1, acc2[2][1]);
            FMA2(acc2[3][0], wb.y, x0, acc2[3][0]); FMA2(acc2[3][1], wb.y, x1, acc2[3][1]);
            FMA2(acc2[4][0], wc.x, x0, acc2[4][0]); FMA2(acc2[4][1], wc.x, x1, acc2[4][1]);
            FMA2(acc2[5][0], wc.y, x0, acc2[5][0]); FMA2(acc2[5][1], wc.y, x1, acc2[5][1]);
        }
    }

    // write out with bias, into attention-friendly layouts
#pragma unroll
    for (int pr = 0; pr < 6; ++pr) {
#pragma unroll
        for (int sub = 0; sub < 2; ++sub) {
            int r = rg * 12 + pr * 2 + sub;
            int p = r >> 5;          // 0=q,1=k,2=v
            int h = (r >> 3) & 3;
            int d = r & 7;
            const float* bias = (p == 0) ? bq : ((p == 1) ? bk : bv);
            float bval = __ldg(&bias[h * 8 + d]);
            int bh = b * 4 + h;
#pragma unroll
            for (int c = 0; c < 2; ++c) {
                int n = n0 + ng * 2 + c;
                float val = (sub ? hi2(acc2[pr][c]) : lo2(acc2[pr][c])) + bval;
                if (p == 0) {
                    // fold log2e (for ex2-based exp) into q
                    g_Q[bh * (NTOK * 8) + (n >> 1) * 16 + d * 2 + (n & 1)] = LOG2E * val;
                } else if (p == 1) {
                    g_K[bh * (NTOK * 8) + n * 8 + d] = val;
                } else {
                    g_V[bh * (NTOK * 8) + (n >> 1) * 16 + d * 2 + (n & 1)] = val;
                }
            }
        }
    }
}

// ============================================================================
// Kernel 2: fused attention core, persistent CTAs + dynamic work stealing.
// Grid = 148 CTAs x 256 threads. 512 items = (bh, sp, mt); item ids are
// mt-fastest so consecutive items reuse the same staged (bh,sp) q/v slice.
// Per item: thread owns 2 m-cols (j=2), streams NSEG=512 n as f32x2 pairs.
// exp via ex2 on the MUFU pipe (log2e folded into q).
// ============================================================================
__global__ void __launch_bounds__(256) attn_kernel()
{
    __shared__ __align__(16) float sq[NSEG * 8];   // 16 KB
    __shared__ __align__(16) float sv[NSEG * 8];   // 16 KB
    __shared__ unsigned s_item;

    const int tid = threadIdx.x;

    for (;;) {
        if (tid == 0) s_item = atomicAdd(&g_ticket, 1u);
        __syncthreads();                    // also protects smem reuse
        const unsigned it = s_item;
        if (it >= N_ITEMS) return;

        const int mt = it & 7;
        const int sp = (it >> 3) & (NSPLIT - 1);
        const int bh = it >> 6;

        // stage q,v slice (contiguous in the interleaved layout)
        const float4* Qb = (const float4*)(g_Q + bh * (NTOK * 8) + sp * (NSEG * 8));
        const float4* Vb = (const float4*)(g_V + bh * (NTOK * 8) + sp * (NSEG * 8));
#pragma unroll
        for (int t = 0; t < 4; ++t) {
            int i = tid + t * 256;
            ((float4*)sq)[i] = Qb[i];
            ((float4*)sv)[i] = Vb[i];
        }

        // k for this thread's 2 m-columns, splatted into f32x2
        ull k2[2][8];
#pragma unroll
        for (int j = 0; j < 2; ++j) {
            int m = mt * 512 + tid + j * 256;
            const float4* kp = (const float4*)(g_K + bh * (NTOK * 8) + m * 8);
            float4 ka = __ldg(kp), kb = __ldg(kp + 1);
            k2[j][0] = splat2(ka.x); k2[j][1] = splat2(ka.y);
            k2[j][2] = splat2(ka.z); k2[j][3] = splat2(ka.w);
            k2[j][4] = splat2(kb.x); k2[j][5] = splat2(kb.y);
            k2[j][6] = splat2(kb.z); k2[j][7] = splat2(kb.w);
        }

        ull num2[2][8], den2[2];
#pragma unroll
        for (int j = 0; j < 2; ++j) {
            den2[j] = 0ull;
#pragma unroll
            for (int d = 0; d < 8; ++d) num2[j][d] = 0ull;
        }

        __syncthreads();

#pragma unroll 2
        for (int p = 0; p < NSEG / 2; ++p) {
            const ulonglong2* qp = (const ulonglong2*)sq + p * 4;
            ull q2[8];
            {
                ulonglong2 t0 = qp[0], t1 = qp[1], t2 = qp[2], t3 = qp[3];
                q2[0] = t0.x; q2[1] = t0.y; q2[2] = t1.x; q2[3] = t1.y;
                q2[4] = t2.x; q2[5] = t2.y; q2[6] = t3.x; q2[7] = t3.y;
            }

            ull s2[2];
#pragma unroll
            for (int j = 0; j < 2; ++j) {
                MUL2(s2[j], q2[0], k2[j][0]);
#pragma unroll
                for (int d = 1; d < 8; ++d) FMA2(s2[j], q2[d], k2[j][d], s2[j]);
            }

            ull e2[2];
#pragma unroll
            for (int j = 0; j < 2; ++j) {
                float el, eh;
                EX2(el, lo2(s2[j]));
                EX2(eh, hi2(s2[j]));
                e2[j] = pack2(el, eh);
                ADD2(den2[j], den2[j], e2[j]);
            }

            const ulonglong2* vp = (const ulonglong2*)sv + p * 4;
            ull v2[8];
            {
                ulonglong2 t0 = vp[0], t1 = vp[1], t2 = vp[2], t3 = vp[3];
                v2[0] = t0.x; v2[1] = t0.y; v2[2] = t1.x; v2[3] = t1.y;
                v2[4] = t2.x; v2[5] = t2.y; v2[6] = t3.x; v2[7] = t3.y;
            }
#pragma unroll
            for (int d = 0; d < 8; ++d)
#pragma unroll
                for (int j = 0; j < 2; ++j)
                    FMA2(num2[j][d], e2[j], v2[d], num2[j][d]);
        }

        // write partials (coalesced over m within warp)
#pragma unroll
        for (int j = 0; j < 2; ++j) {
            int m = mt * 512 + tid + j * 256;
            int base = ((bh * NSPLIT + sp) * 9) * NTOK + m;
#pragma unroll
            for (int d = 0; d < 8; ++d)
                g_P[base + d * NTOK] = lo2(num2[j][d]) + hi2(num2[j][d]);
            g_P[base + 8 * NTOK] = lo2(den2[j]) + hi2(den2[j]);
        }
    }
}

// ============================================================================
// Kernel 3: reduce splits, normalize, Wo projection, gamma, residual.
// Thread per (bh, m, e-half): 65536 threads, each produces 32 outputs.
// ============================================================================
__global__ void __launch_bounds__(256) out_kernel(
    const float* __restrict__ x,
    const float* __restrict__ Wo, const float* __restrict__ bo,
    const float* __restrict__ gamma,
    float* __restrict__ out)
{
    __shared__ float wo_s[256];   // 32 e x 8 d
    __shared__ float bo_s[32];
    __shared__ float gam_s;

    const int t  = blockIdx.x * 256 + threadIdx.x;
    const int m  = t & 4095;
    const int bh = (t >> 12) & 7;
    const int eh = t >> 15;       // e-half 0/1 (uniform per block)
    const int b  = bh >> 2;
    const int h  = bh & 3;

    wo_s[threadIdx.x] = Wo[h * 512 + eh * 256 + threadIdx.x];
    if (threadIdx.x < 32) bo_s[threadIdx.x] = bo[h * 64 + eh * 32 + threadIdx.x];
    if (threadIdx.x == 0) gam_s = gamma[h];
    __syncthreads();

    float num[8];
#pragma unroll
    for (int d = 0; d < 8; ++d) num[d] = 0.0f;
    float den = 0.0f;

#pragma unroll
    for (int s = 0; s < NSPLIT; ++s) {
        const float* P = g_P + ((bh * NSPLIT + s) * 9) * NTOK + m;
#pragma unroll
        for (int d = 0; d < 8; ++d) num[d] += P[d * NTOK];
        den += P[8 * NTOK];
    }

    const float rden = 1.0f / den;
    float o[8];
#pragma unroll
    for (int d = 0; d < 8; ++d) o[d] = num[d] * rden;

    const float gam = gam_s;
#pragma unroll 4
    for (int e = 0; e < 32; ++e) {
        float y = bo_s[e];
#pragma unroll
        for (int d = 0; d < 8; ++d) y += wo_s[e * 8 + d] * o[d];
        int idx = b * (256 * NTOK) + (h * 64 + eh * 32 + e) * NTOK + m;
        out[idx] = gam * y + x[idx];
    }
}

// ============================================================================
extern "C" void kernel_launch(void* const* d_in, const int* in_sizes, int n_in,
                              void* d_out, int out_size)
{
    const float* x     = (const float*)d_in[0];
    const float* Wq    = (const float*)d_in[1];
    const float* bq    = (const float*)d_in[2];
    const float* Wk    = (const float*)d_in[3];
    const float* bk    = (const float*)d_in[4];
    const float* Wv    = (const float*)d_in[5];
    const float* bv    = (const float*)d_in[6];
    const float* Wo    = (const float*)d_in[7];
    const float* bo    = (const float*)d_in[8];
    const float* gamma = (const float*)d_in[9];
    float* out = (float*)d_out;

    qkv_kernel<<<128, 256>>>(x, Wq, bq, Wk, bk, Wv, bv);
    attn_kernel<<<148, 256>>>();
    out_kernel<<<256, 256>>>(x, Wo, bo, gamma, out);
}

// round 7
// speedup vs baseline: 1.1501x; 1.1501x over previous
#include <cuda_runtime.h>

typedef unsigned long long ull;

// ---------------- f32x2 packed math (FFMA2 — PTX-only on sm_103a) ----------
#define FMA2(d,a,b,c) asm("fma.rn.f32x2 %0, %1, %2, %3;" : "=l"(d) : "l"(a), "l"(b), "l"(c))
#define MUL2(d,a,b)   asm("mul.rn.f32x2 %0, %1, %2;"     : "=l"(d) : "l"(a), "l"(b))
#define ADD2(d,a,b)   asm("add.rn.f32x2 %0, %1, %2;"     : "=l"(d) : "l"(a), "l"(b))
#define EX2(d,s)      asm("ex2.approx.f32 %0, %1;"       : "=f"(d) : "f"(s))

__device__ __forceinline__ ull splat2(float f) {
    unsigned u = __float_as_uint(f);
    return ((ull)u << 32) | (ull)u;
}
__device__ __forceinline__ float lo2(ull v) { return __uint_as_float((unsigned)v); }
__device__ __forceinline__ float hi2(ull v) { return __uint_as_float((unsigned)(v >> 32)); }
__device__ __forceinline__ ull pack2(float lo, float hi) {
    return ((ull)__float_as_uint(hi) << 32) | (ull)__float_as_uint(lo);
}

// ---------------- problem constants ----------------------------------------
// B=2, C=256, N=4096, NUM_HEAD=4, D=8, AT_HEAD=64, BH=8
#define NTOK   4096
#define BH_CNT 8
#define NSPLIT 8                 // n-range splits
#define NSEG   (NTOK / NSPLIT)   // 512 n per attn item
#define MT_CNT 8                 // m-tiles of 512 (j=2 per thread)
#define N_ITEMS (BH_CNT * NSPLIT * MT_CNT)   // 512 work items
#define PERSIST_CTAS 296         // 2 per SM

#define LOG2E  1.4426950408889634f

// ---------------- device scratch (no allocation allowed) -------------------
// Q/V: interleaved pair layout [bh][n/2][d*2 + (n&1)]   (q pre-scaled by log2e)
// K  : [bh][n][d]
__device__ float g_Q[BH_CNT * NTOK * 8];
__device__ float g_K[BH_CNT * NTOK * 8];
__device__ float g_V[BH_CNT * NTOK * 8];
// partials: [bh][split][j in 0..8 (8 num + 1 den)][m]
__device__ float g_P[BH_CNT * NSPLIT * 9 * NTOK];
// dynamic work queue ticket (reset by qkv_kernel each launch)
__device__ unsigned g_ticket;

// ============================================================================
// Kernel 1: fused QKV projection, register-tiled GEMM with f32x2 row-pairs.
// C[96 x 8192] = W[96 x 256] @ X[256 x 8192].
// 256 blocks; block = all 96 rows x 32 n. 256 threads:
//   rg = warp id -> 12 rows (6 row-pairs), ng = lane -> 1 n.
// Per scalar k: 3 broadcast LDS.128 (W row-pairs) + 1 LDS.32 (x) + 6 FFMA2.
// ============================================================================
#define WPAD 100   // W smem row stride (floats): mult of 4, bank-spread

__global__ void __launch_bounds__(256, 2) qkv_kernel(
    const float* __restrict__ x,
    const float* __restrict__ Wq, const float* __restrict__ bq,
    const float* __restrict__ Wk, const float* __restrict__ bk,
    const float* __restrict__ Wv, const float* __restrict__ bv)
{
    __shared__ __align__(16) float xs[64 * 32];     // [k_local][n]  8 KB
    __shared__ __align__(16) float ws[64 * WPAD];   // [k_local][r]  25.6 KB

    if (blockIdx.x == 0 && threadIdx.x == 0) g_ticket = 0;  // reset attn queue

    const int b   = blockIdx.x >> 7;            // 256 blocks: 128 per b
    const int n0  = (blockIdx.x & 127) * 32;
    const int tid = threadIdx.x;
    const int rg  = tid >> 5;                   // 0..7, constant per warp
    const int ng  = tid & 31;                   // 1 n each

    ull acc2[6];                                 // [row-pair]
#pragma unroll
    for (int pr = 0; pr < 6; ++pr) acc2[pr] = 0ull;

    for (int kc = 0; kc < 4; ++kc) {
        const int kb = kc * 64;
        __syncthreads();
        // stage x chunk: x[b][kb + c][n0..n0+31]  (512 float4)
#pragma unroll
        for (int t = 0; t < 2; ++t) {
            int idx = tid + t * 256;
            int c   = idx >> 3;
            int nq  = idx & 7;
            float4 xv = __ldg((const float4*)(x + (b * 256 + kb + c) * NTOK + n0) + nq);
            *(float4*)&xs[c * 32 + nq * 4] = xv;
        }
        // stage W chunk: ws[k][r] = W[r][kb + k]
#pragma unroll
        for (int t = 0; t < 6; ++t) {
            int idx = tid + t * 256;
            int r   = idx >> 4;
            int k4  = idx & 15;
            const float* base = (r < 32) ? Wq : ((r < 64) ? Wk : Wv);
            float4 w = __ldg((const float4*)(base + (r & 31) * 256 + kb) + k4);
            ws[(k4 * 4 + 0) * WPAD + r] = w.x;
            ws[(k4 * 4 + 1) * WPAD + r] = w.y;
            ws[(k4 * 4 + 2) * WPAD + r] = w.z;
            ws[(k4 * 4 + 3) * WPAD + r] = w.w;
        }
        __syncthreads();

#pragma unroll 8
        for (int k = 0; k < 64; ++k) {
            ull xv = splat2(xs[k * 32 + ng]);
            const ulonglong2* wr = (const ulonglong2*)&ws[k * WPAD + rg * 12];
            ulonglong2 wa = wr[0], wb = wr[1], wc = wr[2];
            FMA2(acc2[0], wa.x, xv, acc2[0]);
            FMA2(acc2[1], wa.y, xv, acc2[1]);
            FMA2(acc2[2], wb.x, xv, acc2[2]);
            FMA2(acc2[3], wb.y, xv, acc2[3]);
            FMA2(acc2[4], wc.x, xv, acc2[4]);
            FMA2(acc2[5], wc.y, xv, acc2[5]);
        }
    }

    // write out with bias, into attention-friendly layouts
    const int n = n0 + ng;
#pragma unroll
    for (int pr = 0; pr < 6; ++pr) {
#pragma unroll
        for (int sub = 0; sub < 2; ++sub) {
            int r = rg * 12 + pr * 2 + sub;
            int p = r >> 5;          // 0=q,1=k,2=v
            int h = (r >> 3) & 3;
            int d = r & 7;
            const float* bias = (p == 0) ? bq : ((p == 1) ? bk : bv);
            float val = (sub ? hi2(acc2[pr]) : lo2(acc2[pr])) + __ldg(&bias[h * 8 + d]);
            int bh = b * 4 + h;
            if (p == 0) {
                // fold log2e (for ex2-based exp) into q
                g_Q[bh * (NTOK * 8) + (n >> 1) * 16 + d * 2 + (n & 1)] = LOG2E * val;
            } else if (p == 1) {
                g_K[bh * (NTOK * 8) + n * 8 + d] = val;
            } else {
                g_V[bh * (NTOK * 8) + (n >> 1) * 16 + d * 2 + (n & 1)] = val;
            }
        }
    }
}

// ============================================================================
// Kernel 2: fused attention core, persistent CTAs + dynamic work stealing.
// 296 CTAs (2/SM: regs capped to 128 via launch bounds, 32KB smem) x 256 thr.
// 512 items = (bh, sp, mt), mt-fastest for L2 reuse of the staged slice.
// Per item: thread owns 2 m-cols (j=2), streams NSEG=512 n as f32x2 pairs.
// exp via ex2 on the MUFU pipe (log2e folded into q).
// ============================================================================
__global__ void __launch_bounds__(256, 2) attn_kernel()
{
    __shared__ __align__(16) float sq[NSEG * 8];   // 16 KB
    __shared__ __align__(16) float sv[NSEG * 8];   // 16 KB
    __shared__ unsigned s_item;

    const int tid = threadIdx.x;

    for (;;) {
        if (tid == 0) s_item = atomicAdd(&g_ticket, 1u);
        __syncthreads();                    // publishes s_item, protects smem reuse
        const unsigned it = s_item;
        if (it >= N_ITEMS) return;

        const int mt = it & (MT_CNT - 1);
        const int sp = (it >> 3) & (NSPLIT - 1);
        const int bh = it >> 6;

        // stage q,v slice (contiguous in the interleaved layout)
        const float4* Qb = (const float4*)(g_Q + bh * (NTOK * 8) + sp * (NSEG * 8));
        const float4* Vb = (const float4*)(g_V + bh * (NTOK * 8) + sp * (NSEG * 8));
#pragma unroll
        for (int t = 0; t < 4; ++t) {
            int i = tid + t * 256;
            ((float4*)sq)[i] = Qb[i];
            ((float4*)sv)[i] = Vb[i];
        }

        // k for this thread's 2 m-columns, splatted into f32x2
        ull k2[2][8];
#pragma unroll
        for (int j = 0; j < 2; ++j) {
            int m = mt * 512 + tid + j * 256;
            const float4* kp = (const float4*)(g_K + bh * (NTOK * 8) + m * 8);
            float4 ka = __ldg(kp), kb = __ldg(kp + 1);
            k2[j][0] = splat2(ka.x); k2[j][1] = splat2(ka.y);
            k2[j][2] = splat2(ka.z); k2[j][3] = splat2(ka.w);
            k2[j][4] = splat2(kb.x); k2[j][5] = splat2(kb.y);
            k2[j][6] = splat2(kb.z); k2[j][7] = splat2(kb.w);
        }

        ull num2[2][8], den2[2];
#pragma unroll
        for (int j = 0; j < 2; ++j) {
            den2[j] = 0ull;
#pragma unroll
            for (int d = 0; d < 8; ++d) num2[j][d] = 0ull;
        }

        __syncthreads();

#pragma unroll 2
        for (int p = 0; p < NSEG / 2; ++p) {
            const ulonglong2* qp = (const ulonglong2*)sq + p * 4;
            ull q2[8];
            {
                ulonglong2 t0 = qp[0], t1 = qp[1], t2 = qp[2], t3 = qp[3];
                q2[0] = t0.x; q2[1] = t0.y; q2[2] = t1.x; q2[3] = t1.y;
                q2[4] = t2.x; q2[5] = t2.y; q2[6] = t3.x; q2[7] = t3.y;
            }

            ull s2[2];
#pragma unroll
            for (int j = 0; j < 2; ++j) {
                MUL2(s2[j], q2[0], k2[j][0]);
#pragma unroll
                for (int d = 1; d < 8; ++d) FMA2(s2[j], q2[d], k2[j][d], s2[j]);
            }

            ull e2[2];
#pragma unroll
            for (int j = 0; j < 2; ++j) {
                float el, eh;
                EX2(el, lo2(s2[j]));
                EX2(eh, hi2(s2[j]));
                e2[j] = pack2(el, eh);
                ADD2(den2[j], den2[j], e2[j]);
            }

            const ulonglong2* vp = (const ulonglong2*)sv + p * 4;
            ull v2[8];
            {
                ulonglong2 t0 = vp[0], t1 = vp[1], t2 = vp[2], t3 = vp[3];
                v2[0] = t0.x; v2[1] = t0.y; v2[2] = t1.x; v2[3] = t1.y;
                v2[4] = t2.x; v2[5] = t2.y; v2[6] = t3.x; v2[7] = t3.y;
            }
#pragma unroll
            for (int d = 0; d < 8; ++d)
#pragma unroll
                for (int j = 0; j < 2; ++j)
                    FMA2(num2[j][d], e2[j], v2[d], num2[j][d]);
        }

        // write partials (coalesced over m within warp)
#pragma unroll
        for (int j = 0; j < 2; ++j) {
            int m = mt * 512 + tid + j * 256;
            int base = ((bh * NSPLIT + sp) * 9) * NTOK + m;
#pragma unroll
            for (int d = 0; d < 8; ++d)
                g_P[base + d * NTOK] = lo2(num2[j][d]) + hi2(num2[j][d]);
            g_P[base + 8 * NTOK] = lo2(den2[j]) + hi2(den2[j]);
        }
    }
}

// ============================================================================
// Kernel 3: reduce splits, normalize, Wo projection, gamma, residual.
// Thread per (bh, m, e-half): 65536 threads, each produces 32 outputs.
// ============================================================================
__global__ void __launch_bounds__(256) out_kernel(
    const float* __restrict__ x,
    const float* __restrict__ Wo, const float* __restrict__ bo,
    const float* __restrict__ gamma,
    float* __restrict__ out)
{
    __shared__ float wo_s[256];   // 32 e x 8 d
    __shared__ float bo_s[32];
    __shared__ float gam_s;

    const int t  = blockIdx.x * 256 + threadIdx.x;
    const int m  = t & 4095;
    const int bh = (t >> 12) & 7;
    const int eh = t >> 15;       // e-half 0/1 (uniform per block)
    const int b  = bh >> 2;
    const int h  = bh & 3;

    wo_s[threadIdx.x] = Wo[h * 512 + eh * 256 + threadIdx.x];
    if (threadIdx.x < 32) bo_s[threadIdx.x] = bo[h * 64 + eh * 32 + threadIdx.x];
    if (threadIdx.x == 0) gam_s = gamma[h];
    __syncthreads();

    float num[8];
#pragma unroll
    for (int d = 0; d < 8; ++d) num[d] = 0.0f;
    float den = 0.0f;

#pragma unroll
    for (int s = 0; s < NSPLIT; ++s) {
        const float* P = g_P + ((bh * NSPLIT + s) * 9) * NTOK + m;
#pragma unroll
        for (int d = 0; d < 8; ++d) num[d] += P[d * NTOK];
        den += P[8 * NTOK];
    }

    const float rden = 1.0f / den;
    float o[8];
#pragma unroll
    for (int d = 0; d < 8; ++d) o[d] = num[d] * rden;

    const float gam = gam_s;
#pragma unroll 4
    for (int e = 0; e < 32; ++e) {
        float y = bo_s[e];
#pragma unroll
        for (int d = 0; d < 8; ++d) y += wo_s[e * 8 + d] * o[d];
        int idx = b * (256 * NTOK) + (h * 64 + eh * 32 + e) * NTOK + m;
        out[idx] = gam * y + x[idx];
    }
}

// ============================================================================
extern "C" void kernel_launch(void* const* d_in, const int* in_sizes, int n_in,
                              void* d_out, int out_size)
{
    const float* x     = (const float*)d_in[0];
    const float* Wq    = (const float*)d_in[1];
    const float* bq    = (const float*)d_in[2];
    const float* Wk    = (const float*)d_in[3];
    const float* bk    = (const float*)d_in[4];
    const float* Wv    = (const float*)d_in[5];
    const float* bv    = (const float*)d_in[6];
    const float* Wo    = (const float*)d_in[7];
    const float* bo    = (const float*)d_in[8];
    const float* gamma = (const float*)d_in[9];
    float* out = (float*)d_out;

    qkv_kernel<<<256, 256>>>(x, Wq, bq, Wk, bk, Wv, bv);
    attn_kernel<<<PERSIST_CTAS, 256>>>();
    out_kernel<<<256, 256>>>(x, Wo, bo, gamma, out);
}

// round 9
// speedup vs baseline: 1.5032x; 1.3070x over previous
#include <cuda_runtime.h>
#include <cuda_fp16.h>
#include <cstdint>

typedef unsigned long long ull;

// ---------------- f32x2 packed math (PTX-only on sm_103a) ------------------
#define FMA2(d,a,b,c) asm("fma.rn.f32x2 %0, %1, %2, %3;" : "=l"(d) : "l"(a), "l"(b), "l"(c))

__device__ __forceinline__ ull splat2(float f) {
    unsigned u = __float_as_uint(f);
    return ((ull)u << 32) | (ull)u;
}
__device__ __forceinline__ float lo2(ull v) { return __uint_as_float((unsigned)v); }
__device__ __forceinline__ float hi2(ull v) { return __uint_as_float((unsigned)(v >> 32)); }

// ---------------- problem constants ----------------------------------------
// B=2, C=256, N=4096, NUM_HEAD=4, D=8, AT_HEAD=64, BH=8
#define NTOK   4096
#define BH_CNT 8
#define LOG2E  1.4426950408889634f

// ---------------- device scratch (no allocation allowed) -------------------
// gQh/gKh: f16 [bh][n][8]   (q pre-scaled by log2e)
// gVT:     f16 [bh][8][n]   (v transposed: d-major)
// gO:      fp32 [bh][m][8]  (normalized attention output)
__device__ __half g_Qh[BH_CNT * NTOK * 8];
__device__ __half g_Kh[BH_CNT * NTOK * 8];
__device__ __half g_VT[BH_CNT * 8 * NTOK];
__device__ float  g_O [BH_CNT * NTOK * 8];

// ============================================================================
// Kernel 1: fused QKV projection (R6-proven shape: 64-wide n, FFMA2 row-pairs).
// C[96 x 8192] = W[96 x 256] @ X[256 x 8192]; emits f16 q/k ([n][8]) and vT.
// ============================================================================
#define WPAD 100

__global__ void __launch_bounds__(256) qkv_kernel(
    const float* __restrict__ x,
    const float* __restrict__ Wq, const float* __restrict__ bq,
    const float* __restrict__ Wk, const float* __restrict__ bk,
    const float* __restrict__ Wv, const float* __restrict__ bv)
{
    __shared__ __align__(16) float xs[64 * 64];     // [k_local][n]  16 KB
    __shared__ __align__(16) float ws[64 * WPAD];   // [k_local][r]  25.6 KB

    const int b   = blockIdx.x >> 6;            // 128 blocks: 64 per b
    const int n0  = (blockIdx.x & 63) * 64;
    const int tid = threadIdx.x;
    const int rg  = tid >> 5;
    const int ng  = tid & 31;                   // 2 n each

    ull acc2[6][2];
#pragma unroll
    for (int pr = 0; pr < 6; ++pr) { acc2[pr][0] = 0ull; acc2[pr][1] = 0ull; }

    for (int kc = 0; kc < 4; ++kc) {
        const int kb = kc * 64;
        __syncthreads();
#pragma unroll
        for (int t = 0; t < 4; ++t) {
            int idx = tid + t * 256;
            int c   = idx >> 4;
            int nq  = idx & 15;
            float4 xv = __ldg((const float4*)(x + (b * 256 + kb + c) * NTOK + n0) + nq);
            *(float4*)&xs[c * 64 + nq * 4] = xv;
        }
#pragma unroll
        for (int t = 0; t < 6; ++t) {
            int idx = tid + t * 256;
            int r   = idx >> 4;
            int k4  = idx & 15;
            const float* base = (r < 32) ? Wq : ((r < 64) ? Wk : Wv);
            float4 w = __ldg((const float4*)(base + (r & 31) * 256 + kb) + k4);
            ws[(k4 * 4 + 0) * WPAD + r] = w.x;
            ws[(k4 * 4 + 1) * WPAD + r] = w.y;
            ws[(k4 * 4 + 2) * WPAD + r] = w.z;
            ws[(k4 * 4 + 3) * WPAD + r] = w.w;
        }
        __syncthreads();

#pragma unroll 8
        for (int k = 0; k < 64; ++k) {
            float2 xv = *(const float2*)&xs[k * 64 + ng * 2];
            ull x0 = splat2(xv.x);
            ull x1 = splat2(xv.y);
            const ulonglong2* wr = (const ulonglong2*)&ws[k * WPAD + rg * 12];
            ulonglong2 wa = wr[0], wb = wr[1], wc = wr[2];
            FMA2(acc2[0][0], wa.x, x0, acc2[0][0]); FMA2(acc2[0][1], wa.x, x1, acc2[0][1]);
            FMA2(acc2[1][0], wa.y, x0, acc2[1][0]); FMA2(acc2[1][1], wa.y, x1, acc2[1][1]);
            FMA2(acc2[2][0], wb.x, x0, acc2[2][0]); FMA2(acc2[2][1], wb.x, x1, acc2[2][1]);
            FMA2(acc2[3][0], wb.y, x0, acc2[3][0]); FMA2(acc2[3][1], wb.y, x1, acc2[3][1]);
            FMA2(acc2[4][0], wc.x, x0, acc2[4][0]); FMA2(acc2[4][1], wc.x, x1, acc2[4][1]);
            FMA2(acc2[5][0], wc.y, x0, acc2[5][0]); FMA2(acc2[5][1], wc.y, x1, acc2[5][1]);
        }
    }

    // write f16 outputs
#pragma unroll
    for (int pr = 0; pr < 6; ++pr) {
#pragma unroll
        for (int sub = 0; sub < 2; ++sub) {
            int r = rg * 12 + pr * 2 + sub;
            int p = r >> 5;          // 0=q,1=k,2=v
            int h = (r >> 3) & 3;
            int d = r & 7;
            const float* bias = (p == 0) ? bq : ((p == 1) ? bk : bv);
            float bval = __ldg(&bias[h * 8 + d]);
            int bh = b * 4 + h;
#pragma unroll
            for (int c = 0; c < 2; ++c) {
                int n = n0 + ng * 2 + c;
                float val = (sub ? hi2(acc2[pr][c]) : lo2(acc2[pr][c])) + bval;
                if (p == 0) {
                    g_Qh[(bh * NTOK + n) * 8 + d] = __float2half_rn(LOG2E * val);
                } else if (p == 1) {
                    g_Kh[(bh * NTOK + n) * 8 + d] = __float2half_rn(val);
                } else {
                    g_VT[(bh * 8 + d) * NTOK + n] = __float2half_rn(val);
                }
            }
        }
    }
}

// ============================================================================
// Kernel 2: warp-MMA (HMMA) attention. 512 CTAs x 128 threads (4 warps).
// CTA item = (bh, 64-m block); warp owns 16 m rows, loops n in steps of 16.
//   GEMM1: S[16m x 16n] fp32 = K_frag · Q_fragᵀ   (2x mma.m16n8k8.f16.f32)
//   epi:   E = ex2(S) as f16x2 — regs already in m16n8k16 A-fragment layout
//   GEMM2: O[16m x 8d] fp32 += E · V_frag          (1x mma.m16n8k16)
//   den:   fp32 accumulation from E regs + quad shuffle reduce at the end.
// ============================================================================
__global__ void __launch_bounds__(128) attn_kernel()
{
    const int warp = threadIdx.x >> 5;
    const int lane = threadIdx.x & 31;
    const int bh   = blockIdx.x >> 6;        // 512 blocks: 64 m-blocks per bh
    const int mb   = blockIdx.x & 63;
    const int m0   = mb * 64 + warp * 16;
    const int g    = lane >> 2;              // fragment row group 0..7
    const int q4   = lane & 3;               // fragment quad col 0..3

    const __half* Kbase = g_Kh + (size_t)bh * NTOK * 8;
    const __half* Qbase = g_Qh + (size_t)bh * NTOK * 8;
    const __half* Vbase = g_VT + (size_t)bh * 8 * NTOK;

    // A fragment: K tokens m0..m0+15, d 0..7 (row-major m16k8)
    const uint32_t aK0 = *(const uint32_t*)(Kbase + (m0 + g) * 8 + q4 * 2);
    const uint32_t aK1 = *(const uint32_t*)(Kbase + (m0 + g + 8) * 8 + q4 * 2);

    float o0 = 0.f, o1 = 0.f, o2 = 0.f, o3 = 0.f;   // GEMM2 accum (rows g, g+8)
    float denA = 0.f, denB = 0.f;

    const __half* vrow = Vbase + g * NTOK;          // V^T row for d = g

#pragma unroll 2
    for (int n0 = 0; n0 < NTOK; n0 += 16) {
        // Q B-fragments (col-major k8 x n8): token n0+g (tile0), n0+8+g (tile1)
        uint32_t bQ0 = *(const uint32_t*)(Qbase + (n0 + g) * 8 + q4 * 2);
        uint32_t bQ1 = *(const uint32_t*)(Qbase + (n0 + 8 + g) * 8 + q4 * 2);
        // V B-fragment (col-major k16 x n8): d = g, tokens n0+2q4{,+1}, +8
        uint32_t bV0 = *(const uint32_t*)(vrow + n0 + q4 * 2);
        uint32_t bV1 = *(const uint32_t*)(vrow + n0 + 8 + q4 * 2);

        // GEMM1: two m16n8k8 MMAs -> S tile rows {g, g+8} x 16 n
        float s0, s1, s2, s3, t0, t1, t2, t3;
        asm volatile(
            "mma.sync.aligned.m16n8k8.row.col.f32.f16.f16.f32 "
            "{%0,%1,%2,%3}, {%4,%5}, {%6}, {%7,%8,%9,%10};"
            : "=f"(s0), "=f"(s1), "=f"(s2), "=f"(s3)
            : "r"(aK0), "r"(aK1), "r"(bQ0),
              "f"(0.f), "f"(0.f), "f"(0.f), "f"(0.f));
        asm volatile(
            "mma.sync.aligned.m16n8k8.row.col.f32.f16.f16.f32 "
            "{%0,%1,%2,%3}, {%4,%5}, {%6}, {%7,%8,%9,%10};"
            : "=f"(t0), "=f"(t1), "=f"(t2), "=f"(t3)
            : "r"(aK0), "r"(aK1), "r"(bQ1),
              "f"(0.f), "f"(0.f), "f"(0.f), "f"(0.f));

        // E = ex2(S): pack fp32 pairs -> f16x2 -> MUFU ex2.f16x2
        uint32_t h0, h1, h2, h3, e0, e1, e2, e3;
        asm("cvt.rn.f16x2.f32 %0, %1, %2;" : "=r"(h0) : "f"(s1), "f"(s0));
        asm("cvt.rn.f16x2.f32 %0, %1, %2;" : "=r"(h1) : "f"(s3), "f"(s2));
        asm("cvt.rn.f16x2.f32 %0, %1, %2;" : "=r"(h2) : "f"(t1), "f"(t0));
        asm("cvt.rn.f16x2.f32 %0, %1, %2;" : "=r"(h3) : "f"(t3), "f"(t2));
        asm("ex2.approx.f16x2 %0, %1;" : "=r"(e0) : "r"(h0));
        asm("ex2.approx.f16x2 %0, %1;" : "=r"(e1) : "r"(h1));
        asm("ex2.approx.f16x2 %0, %1;" : "=r"(e2) : "r"(h2));
        asm("ex2.approx.f16x2 %0, %1;" : "=r"(e3) : "r"(h3));

        // den accumulation (fp32): row g from e0,e2; row g+8 from e1,e3
        {
            __half2 hA = __hadd2(*(__half2*)&e0, *(__half2*)&e2);
            __half2 hB = __hadd2(*(__half2*)&e1, *(__half2*)&e3);
            float2 fA = __half22float2(hA);
            float2 fB = __half22float2(hB);
            denA += fA.x + fA.y;
            denB += fB.x + fB.y;
        }

        // GEMM2: O += E · V  (E regs are exactly the m16n8k16 A fragment)
        asm volatile(
            "mma.sync.aligned.m16n8k16.row.col.f32.f16.f16.f32 "
            "{%0,%1,%2,%3}, {%4,%5,%6,%7}, {%8,%9}, {%0,%1,%2,%3};"
            : "+f"(o0), "+f"(o1), "+f"(o2), "+f"(o3)
            : "r"(e0), "r"(e1), "r"(e2), "r"(e3), "r"(bV0), "r"(bV1));
    }

    // quad-reduce den over the 4 lanes sharing each row
    denA += __shfl_xor_sync(0xFFFFFFFFu, denA, 1);
    denA += __shfl_xor_sync(0xFFFFFFFFu, denA, 2);
    denB += __shfl_xor_sync(0xFFFFFFFFu, denB, 1);
    denB += __shfl_xor_sync(0xFFFFFFFFu, denB, 2);
    const float rA = 1.0f / denA;
    const float rB = 1.0f / denB;

    // store normalized output: rows m0+g (o0,o1), m0+g+8 (o2,o3), cols 2q4,2q4+1
    float* OpA = g_O + ((size_t)(bh * NTOK + m0 + g)) * 8 + q4 * 2;
    float* OpB = g_O + ((size_t)(bh * NTOK + m0 + g + 8)) * 8 + q4 * 2;
    *(float2*)OpA = make_float2(o0 * rA, o1 * rA);
    *(float2*)OpB = make_float2(o2 * rB, o3 * rB);
}

// ============================================================================
// Kernel 3: Wo projection + bias + gamma + residual.
// Thread per (bh, m, e-half): 65536 threads -> 256 blocks.
// ============================================================================
__global__ void __launch_bounds__(256) out_kernel(
    const float* __restrict__ x,
    const float* __restrict__ Wo, const float* __restrict__ bo,
    const float* __restrict__ gamma,
    float* __restrict__ out)
{
    __shared__ float wo_s[256];   // 32 e x 8 d
    __shared__ float bo_s[32];
    __shared__ float gam_s;

    const int t  = blockIdx.x * 256 + threadIdx.x;
    const int m  = t & 4095;
    const int bh = (t >> 12) & 7;
    const int eh = t >> 15;       // e-half (uniform per block)
    const int b  = bh >> 2;
    const int h  = bh & 3;

    wo_s[threadIdx.x] = Wo[h * 512 + eh * 256 + threadIdx.x];
    if (threadIdx.x < 32) bo_s[threadIdx.x] = bo[h * 64 + eh * 32 + threadIdx.x];
    if (threadIdx.x == 0) gam_s = gamma[h];
    __syncthreads();

    const float4* op = (const float4*)(g_O + (size_t)(bh * NTOK + m) * 8);
    float4 a = op[0], c = op[1];
    float o[8] = {a.x, a.y, a.z, a.w, c.x, c.y, c.z, c.w};

    const float gam = gam_s;
#pragma unroll 4
    for (int e = 0; e < 32; ++e) {
        float y = bo_s[e];
#pragma unroll
        for (int d = 0; d < 8; ++d) y += wo_s[e * 8 + d] * o[d];
        int idx = b * (256 * NTOK) + (h * 64 + eh * 32 + e) * NTOK + m;
        out[idx] = gam * y + x[idx];
    }
}

// ============================================================================
extern "C" void kernel_launch(void* const* d_in, const int* in_sizes, int n_in,
                              void* d_out, int out_size)
{
    const float* x     = (const float*)d_in[0];
    const float* Wq    = (const float*)d_in[1];
    const float* bq    = (const float*)d_in[2];
    const float* Wk    = (const float*)d_in[3];
    const float* bk    = (const float*)d_in[4];
    const float* Wv    = (const float*)d_in[5];
    const float* bv    = (const float*)d_in[6];
    const float* Wo    = (const float*)d_in[7];
    const float* bo    = (const float*)d_in[8];
    const float* gamma = (const float*)d_in[9];
    float* out = (float*)d_out;

    qkv_kernel<<<128, 256>>>(x, Wq, bq, Wk, bk, Wv, bv);
    attn_kernel<<<512, 128>>>();
    out_kernel<<<256, 256>>>(x, Wo, bo, gamma, out);
}

// round 10
// speedup vs baseline: 2.8765x; 1.9136x over previous
#include <cuda_runtime.h>
#include <cuda_fp16.h>
#include <cstdint>

typedef unsigned long long ull;

// ---------------- f32x2 packed math (PTX-only on sm_103a) ------------------
#define FMA2(d,a,b,c) asm("fma.rn.f32x2 %0, %1, %2, %3;" : "=l"(d) : "l"(a), "l"(b), "l"(c))

__device__ __forceinline__ ull splat2(float f) {
    unsigned u = __float_as_uint(f);
    return ((ull)u << 32) | (ull)u;
}
__device__ __forceinline__ float lo2(ull v) { return __uint_as_float((unsigned)v); }
__device__ __forceinline__ float hi2(ull v) { return __uint_as_float((unsigned)(v >> 32)); }

// ---------------- problem constants ----------------------------------------
// B=2, C=256, N=4096, NUM_HEAD=4, D=8, AT_HEAD=64, BH=8
#define NTOK   4096
#define BH_CNT 8
#define LOG2E  1.4426950408889634f

// ---------------- device scratch (no allocation allowed) -------------------
// gQh/gKh: f16 [bh][n][8]   (q pre-scaled by log2e)
// gVT:     f16 [bh][8][n]   (v transposed: d-major)
// gO:      fp32 [bh][m][8]  (normalized attention output)
__device__ __half g_Qh[BH_CNT * NTOK * 8];
__device__ __half g_Kh[BH_CNT * NTOK * 8];
__device__ __half g_VT[BH_CNT * 8 * NTOK];
__device__ float  g_O [BH_CNT * NTOK * 8];

// ============================================================================
// Kernel 1: fused QKV projection, FFMA2 row-pairs + software-pipelined chunks.
// C[96 x 8192] = W[96 x 256] @ X[256 x 8192]; emits f16 q/k ([n][8]) and vT.
// Chunk k+1's gmem loads are prefetched into registers during chunk k compute.
// ============================================================================
#define WPAD 100

__global__ void __launch_bounds__(256) qkv_kernel(
    const float* __restrict__ x,
    const float* __restrict__ Wq, const float* __restrict__ bq,
    const float* __restrict__ Wk, const float* __restrict__ bk,
    const float* __restrict__ Wv, const float* __restrict__ bv)
{
    __shared__ __align__(16) float xs[64 * 64];     // [k_local][n]  16 KB
    __shared__ __align__(16) float ws[64 * WPAD];   // [k_local][r]  25.6 KB

    const int b   = blockIdx.x >> 6;            // 128 blocks: 64 per b
    const int n0  = (blockIdx.x & 63) * 64;
    const int tid = threadIdx.x;
    const int rg  = tid >> 5;
    const int ng  = tid & 31;                   // 2 n each

    ull acc2[6][2];
#pragma unroll
    for (int pr = 0; pr < 6; ++pr) { acc2[pr][0] = 0ull; acc2[pr][1] = 0ull; }

    // prefetch registers (chunk 0)
    float4 px[4], pw[6];
#pragma unroll
    for (int t = 0; t < 4; ++t) {
        int idx = tid + t * 256;
        int c   = idx >> 4;
        int nq  = idx & 15;
        px[t] = __ldg((const float4*)(x + (b * 256 + c) * NTOK + n0) + nq);
    }
#pragma unroll
    for (int t = 0; t < 6; ++t) {
        int idx = tid + t * 256;
        int r   = idx >> 4;
        int k4  = idx & 15;
        const float* base = (r < 32) ? Wq : ((r < 64) ? Wk : Wv);
        pw[t] = __ldg((const float4*)(base + (r & 31) * 256) + k4);
    }

    for (int kc = 0; kc < 4; ++kc) {
        __syncthreads();      // previous compute finished reading smem
        // commit prefetched chunk to smem
#pragma unroll
        for (int t = 0; t < 4; ++t) {
            int idx = tid + t * 256;
            int c   = idx >> 4;
            int nq  = idx & 15;
            *(float4*)&xs[c * 64 + nq * 4] = px[t];
        }
#pragma unroll
        for (int t = 0; t < 6; ++t) {
            int idx = tid + t * 256;
            int k4  = idx & 15;
            int r   = idx >> 4;
            ws[(k4 * 4 + 0) * WPAD + r] = pw[t].x;
            ws[(k4 * 4 + 1) * WPAD + r] = pw[t].y;
            ws[(k4 * 4 + 2) * WPAD + r] = pw[t].z;
            ws[(k4 * 4 + 3) * WPAD + r] = pw[t].w;
        }
        // prefetch next chunk (overlaps with compute below)
        if (kc < 3) {
            const int kb = (kc + 1) * 64;
#pragma unroll
            for (int t = 0; t < 4; ++t) {
                int idx = tid + t * 256;
                int c   = idx >> 4;
                int nq  = idx & 15;
                px[t] = __ldg((const float4*)(x + (b * 256 + kb + c) * NTOK + n0) + nq);
            }
#pragma unroll
            for (int t = 0; t < 6; ++t) {
                int idx = tid + t * 256;
                int r   = idx >> 4;
                int k4  = idx & 15;
                const float* base = (r < 32) ? Wq : ((r < 64) ? Wk : Wv);
                pw[t] = __ldg((const float4*)(base + (r & 31) * 256 + kb) + k4);
            }
        }
        __syncthreads();

#pragma unroll 8
        for (int k = 0; k < 64; ++k) {
            float2 xv = *(const float2*)&xs[k * 64 + ng * 2];
            ull x0 = splat2(xv.x);
            ull x1 = splat2(xv.y);
            const ulonglong2* wr = (const ulonglong2*)&ws[k * WPAD + rg * 12];
            ulonglong2 wa = wr[0], wb = wr[1], wc = wr[2];
            FMA2(acc2[0][0], wa.x, x0, acc2[0][0]); FMA2(acc2[0][1], wa.x, x1, acc2[0][1]);
            FMA2(acc2[1][0], wa.y, x0, acc2[1][0]); FMA2(acc2[1][1], wa.y, x1, acc2[1][1]);
            FMA2(acc2[2][0], wb.x, x0, acc2[2][0]); FMA2(acc2[2][1], wb.x, x1, acc2[2][1]);
            FMA2(acc2[3][0], wb.y, x0, acc2[3][0]); FMA2(acc2[3][1], wb.y, x1, acc2[3][1]);
            FMA2(acc2[4][0], wc.x, x0, acc2[4][0]); FMA2(acc2[4][1], wc.x, x1, acc2[4][1]);
            FMA2(acc2[5][0], wc.y, x0, acc2[5][0]); FMA2(acc2[5][1], wc.y, x1, acc2[5][1]);
        }
    }

    // write f16 outputs
#pragma unroll
    for (int pr = 0; pr < 6; ++pr) {
#pragma unroll
        for (int sub = 0; sub < 2; ++sub) {
            int r = rg * 12 + pr * 2 + sub;
            int p = r >> 5;          // 0=q,1=k,2=v
            int h = (r >> 3) & 3;
            int d = r & 7;
            const float* bias = (p == 0) ? bq : ((p == 1) ? bk : bv);
            float bval = __ldg(&bias[h * 8 + d]);
            int bh = b * 4 + h;
#pragma unroll
            for (int c = 0; c < 2; ++c) {
                int n = n0 + ng * 2 + c;
                float val = (sub ? hi2(acc2[pr][c]) : lo2(acc2[pr][c])) + bval;
                if (p == 0) {
                    g_Qh[(bh * NTOK + n) * 8 + d] = __float2half_rn(LOG2E * val);
                } else if (p == 1) {
                    g_Kh[(bh * NTOK + n) * 8 + d] = __float2half_rn(val);
                } else {
                    g_VT[(bh * 8 + d) * NTOK + n] = __float2half_rn(val);
                }
            }
        }
    }
}

// ============================================================================
// Kernel 2: warp-MMA (HMMA) attention with smem-staged Q/V slabs.
// 256 CTAs x 256 threads (8 warps). CTA item = (bh, 128-m block);
// warp owns 16 m rows. Outer loop: 8 slabs of 512 n staged in smem;
// inner loop: 32 steps of 16 n, all operand reads are conflict-free LDS.
//   GEMM1: S[16m x 16n] fp32 = K_frag · Q_fragᵀ   (2x mma.m16n8k8)
//   epi:   E = ex2(S) as f16x2 (m16n8k16 A-fragment layout)
//   GEMM2: O[16m x 8d] fp32 += E · V_frag          (1x mma.m16n8k16)
// ============================================================================
#define VPAD 520   // sVT row stride in halves (1040B = 65*16: f4-aligned, bank-spread)

__global__ void __launch_bounds__(256) attn_kernel()
{
    __shared__ __align__(16) __half sQ[512 * 8];      // [token][d]  8 KB
    __shared__ __align__(16) __half sVT[8 * VPAD];    // [d][n+pad]  8.1 KB

    const int tid  = threadIdx.x;
    const int warp = tid >> 5;
    const int lane = tid & 31;
    const int bh   = blockIdx.x >> 5;        // 256 blocks: 32 m-blocks per bh
    const int mb   = blockIdx.x & 31;
    const int m0   = mb * 128 + warp * 16;
    const int g    = lane >> 2;              // fragment row group 0..7
    const int q4   = lane & 3;               // fragment quad col 0..3

    // A fragment: K tokens m0..m0+15, d 0..7 (row-major m16k8) — loaded once
    const __half* Kbase = g_Kh + (size_t)bh * NTOK * 8;
    const uint32_t aK0 = *(const uint32_t*)(Kbase + (m0 + g) * 8 + q4 * 2);
    const uint32_t aK1 = *(const uint32_t*)(Kbase + (m0 + g + 8) * 8 + q4 * 2);

    float o0 = 0.f, o1 = 0.f, o2 = 0.f, o3 = 0.f;
    float denA = 0.f, denB = 0.f;

    const int vd = tid >> 5;    // staging: row d for this warp
    const int vj = tid & 31;

    for (int ns = 0; ns < 8; ++ns) {
        __syncthreads();   // previous inner loop done with smem
        // stage Q slab: 512 tokens x 8 halves = 512 float4
        {
            const float4* Qs = (const float4*)(g_Qh + (size_t)bh * NTOK * 8 + ns * 512 * 8);
            ((float4*)sQ)[tid]       = Qs[tid];
            ((float4*)sQ)[tid + 256] = Qs[tid + 256];
        }
        // stage V slab: 8 rows x 512 halves (64 float4 per row)
        {
            const float4* Vs = (const float4*)(g_VT + (size_t)(bh * 8 + vd) * NTOK + ns * 512);
            float4* dst = (float4*)(sVT + vd * VPAD);
            dst[vj]      = Vs[vj];
            dst[vj + 32] = Vs[vj + 32];
        }
        __syncthreads();

#pragma unroll 4
        for (int p = 0; p < 32; ++p) {
            const int n0 = p * 16;
            // Q B-fragments (col-major k8 x n8)
            uint32_t bQ0 = *(const uint32_t*)(sQ + (n0 + g) * 8 + q4 * 2);
            uint32_t bQ1 = *(const uint32_t*)(sQ + (n0 + 8 + g) * 8 + q4 * 2);
            // V B-fragment (col-major k16 x n8): d = g
            uint32_t bV0 = *(const uint32_t*)(sVT + g * VPAD + n0 + q4 * 2);
            uint32_t bV1 = *(const uint32_t*)(sVT + g * VPAD + n0 + 8 + q4 * 2);

            float s0, s1, s2, s3, t0, t1, t2, t3;
            asm volatile(
                "mma.sync.aligned.m16n8k8.row.col.f32.f16.f16.f32 "
                "{%0,%1,%2,%3}, {%4,%5}, {%6}, {%7,%8,%9,%10};"
                : "=f"(s0), "=f"(s1), "=f"(s2), "=f"(s3)
                : "r"(aK0), "r"(aK1), "r"(bQ0),
                  "f"(0.f), "f"(0.f), "f"(0.f), "f"(0.f));
            asm volatile(
                "mma.sync.aligned.m16n8k8.row.col.f32.f16.f16.f32 "
                "{%0,%1,%2,%3}, {%4,%5}, {%6}, {%7,%8,%9,%10};"
                : "=f"(t0), "=f"(t1), "=f"(t2), "=f"(t3)
                : "r"(aK0), "r"(aK1), "r"(bQ1),
                  "f"(0.f), "f"(0.f), "f"(0.f), "f"(0.f));

            uint32_t h0, h1, h2, h3, e0, e1, e2, e3;
            asm("cvt.rn.f16x2.f32 %0, %1, %2;" : "=r"(h0) : "f"(s1), "f"(s0));
            asm("cvt.rn.f16x2.f32 %0, %1, %2;" : "=r"(h1) : "f"(s3), "f"(s2));
            asm("cvt.rn.f16x2.f32 %0, %1, %2;" : "=r"(h2) : "f"(t1), "f"(t0));
            asm("cvt.rn.f16x2.f32 %0, %1, %2;" : "=r"(h3) : "f"(t3), "f"(t2));
            asm("ex2.approx.f16x2 %0, %1;" : "=r"(e0) : "r"(h0));
            asm("ex2.approx.f16x2 %0, %1;" : "=r"(e1) : "r"(h1));
            asm("ex2.approx.f16x2 %0, %1;" : "=r"(e2) : "r"(h2));
            asm("ex2.approx.f16x2 %0, %1;" : "=r"(e3) : "r"(h3));

            // den accumulation (fp32): row g from e0,e2; row g+8 from e1,e3
            {
                __half2 hA = __hadd2(*(__half2*)&e0, *(__half2*)&e2);
                __half2 hB = __hadd2(*(__half2*)&e1, *(__half2*)&e3);
                float2 fA = __half22float2(hA);
                float2 fB = __half22float2(hB);
                denA += fA.x + fA.y;
                denB += fB.x + fB.y;
            }

            asm volatile(
                "mma.sync.aligned.m16n8k16.row.col.f32.f16.f16.f32 "
                "{%0,%1,%2,%3}, {%4,%5,%6,%7}, {%8,%9}, {%0,%1,%2,%3};"
                : "+f"(o0), "+f"(o1), "+f"(o2), "+f"(o3)
                : "r"(e0), "r"(e1), "r"(e2), "r"(e3), "r"(bV0), "r"(bV1));
        }
    }

    // quad-reduce den over the 4 lanes sharing each row
    denA += __shfl_xor_sync(0xFFFFFFFFu, denA, 1);
    denA += __shfl_xor_sync(0xFFFFFFFFu, denA, 2);
    denB += __shfl_xor_sync(0xFFFFFFFFu, denB, 1);
    denB += __shfl_xor_sync(0xFFFFFFFFu, denB, 2);
    const float rA = 1.0f / denA;
    const float rB = 1.0f / denB;

    float* OpA = g_O + ((size_t)(bh * NTOK + m0 + g)) * 8 + q4 * 2;
    float* OpB = g_O + ((size_t)(bh * NTOK + m0 + g + 8)) * 8 + q4 * 2;
    *(float2*)OpA = make_float2(o0 * rA, o1 * rA);
    *(float2*)OpB = make_float2(o2 * rB, o3 * rB);
}

// ============================================================================
// Kernel 3: Wo projection + bias + gamma + residual.
// Thread per (bh, m, e-half): 65536 threads -> 256 blocks.
// ============================================================================
__global__ void __launch_bounds__(256) out_kernel(
    const float* __restrict__ x,
    const float* __restrict__ Wo, const float* __restrict__ bo,
    const float* __restrict__ gamma,
    float* __restrict__ out)
{
    __shared__ float wo_s[256];   // 32 e x 8 d
    __shared__ float bo_s[32];
    __shared__ float gam_s;

    const int t  = blockIdx.x * 256 + threadIdx.x;
    const int m  = t & 4095;
    const int bh = (t >> 12) & 7;
    const int eh = t >> 15;       // e-half (uniform per block)
    const int b  = bh >> 2;
    const int h  = bh & 3;

    wo_s[threadIdx.x] = Wo[h * 512 + eh * 256 + threadIdx.x];
    if (threadIdx.x < 32) bo_s[threadIdx.x] = bo[h * 64 + eh * 32 + threadIdx.x];
    if (threadIdx.x == 0) gam_s = gamma[h];
    __syncthreads();

    const float4* op = (const float4*)(g_O + (size_t)(bh * NTOK + m) * 8);
    float4 a = op[0], c = op[1];
    float o[8] = {a.x, a.y, a.z, a.w, c.x, c.y, c.z, c.w};

    const float gam = gam_s;
#pragma unroll 4
    for (int e = 0; e < 32; ++e) {
        float y = bo_s[e];
#pragma unroll
        for (int d = 0; d < 8; ++d) y += wo_s[e * 8 + d] * o[d];
        int idx = b * (256 * NTOK) + (h * 64 + eh * 32 + e) * NTOK + m;
        out[idx] = gam * y + x[idx];
    }
}

// ============================================================================
extern "C" void kernel_launch(void* const* d_in, const int* in_sizes, int n_in,
                              void* d_out, int out_size)
{
    const float* x     = (const float*)d_in[0];
    const float* Wq    = (const float*)d_in[1];
    const float* bq    = (const float*)d_in[2];
    const float* Wk    = (const float*)d_in[3];
    const float* bk    = (const float*)d_in[4];
    const float* Wv    = (const float*)d_in[5];
    const float* bv    = (const float*)d_in[6];
    const float* Wo    = (const float*)d_in[7];
    const float* bo    = (const float*)d_in[8];
    const float* gamma = (const float*)d_in[9];
    float* out = (float*)d_out;

    qkv_kernel<<<128, 256>>>(x, Wq, bq, Wk, bk, Wv, bv);
    attn_kernel<<<256, 256>>>();
    out_kernel<<<256, 256>>>(x, Wo, bo, gamma, out);
}

// round 12
// speedup vs baseline: 2.9788x; 1.0356x over previous
#include <cuda_runtime.h>
#include <cuda_fp16.h>
#include <cstdint>

typedef unsigned long long ull;

// ---------------- f32x2 packed math (PTX-only on sm_103a) ------------------
#define FMA2(d,a,b,c) asm("fma.rn.f32x2 %0, %1, %2, %3;" : "=l"(d) : "l"(a), "l"(b), "l"(c))

__device__ __forceinline__ ull splat2(float f) {
    unsigned u = __float_as_uint(f);
    return ((ull)u << 32) | (ull)u;
}
__device__ __forceinline__ float lo2(ull v) { return __uint_as_float((unsigned)v); }
__device__ __forceinline__ float hi2(ull v) { return __uint_as_float((unsigned)(v >> 32)); }

// ---------------- problem constants ----------------------------------------
// B=2, C=256, N=4096, NUM_HEAD=4, D=8, AT_HEAD=64, BH=8
#define NTOK   4096
#define BH_CNT 8
#define LOG2E  1.4426950408889634f

// ---------------- device scratch (no allocation allowed) -------------------
// gQh/gKh: f16 [bh][n][8]   (q pre-scaled by log2e)
// gVT:     f16 [bh][8][n]   (v transposed: d-major)
// gO:      fp32 [bh][m][8]  (normalized attention output)
__device__ __half g_Qh[BH_CNT * NTOK * 8];
__device__ __half g_Kh[BH_CNT * NTOK * 8];
__device__ __half g_VT[BH_CNT * 8 * NTOK];
__device__ float  g_O [BH_CNT * NTOK * 8];

// ============================================================================
// Kernel 1: fused QKV projection, FFMA2 row-pairs, software-pipelined chunks.
// C[96 x 8192] = W[96 x 256] @ X[256 x 8192]; emits f16 q/k ([n][8]) and vT.
// 256 CTAs = b(2) x row-half(2) x n-tile(64): each CTA does 48 rows x 64 n.
// Warp = 6 rows (3 f32x2 row-pairs); per k: 4 broadcast LDS.64 + 6 FFMA2.
// ============================================================================
#define WPAD 52   // W smem row stride (floats)

__global__ void __launch_bounds__(256, 2) qkv_kernel(
    const float* __restrict__ x,
    const float* __restrict__ Wq, const float* __restrict__ bq,
    const float* __restrict__ Wk, const float* __restrict__ bk,
    const float* __restrict__ Wv, const float* __restrict__ bv)
{
    __shared__ __align__(16) float xs[64 * 64];     // [k_local][n]  16 KB
    __shared__ __align__(16) float ws[64 * WPAD];   // [k_local][r]  13.3 KB

    const int b   = blockIdx.x >> 7;            // 256 blocks
    const int rh  = (blockIdx.x >> 6) & 1;      // row half: rows rh*48 .. +47
    const int n0  = (blockIdx.x & 63) * 64;
    const int tid = threadIdx.x;
    const int rg  = tid >> 5;                   // warp: 6 rows each
    const int ng  = tid & 31;                   // 2 n each

    ull acc2[3][2];
#pragma unroll
    for (int pr = 0; pr < 3; ++pr) { acc2[pr][0] = 0ull; acc2[pr][1] = 0ull; }

    // prefetch registers (chunk 0)
    float4 px[4], pw[3];
#pragma unroll
    for (int t = 0; t < 4; ++t) {
        int idx = tid + t * 256;
        int c   = idx >> 4;
        int nq  = idx & 15;
        px[t] = __ldg((const float4*)(x + (b * 256 + c) * NTOK + n0) + nq);
    }
#pragma unroll
    for (int t = 0; t < 3; ++t) {
        int idx = tid + t * 256;
        int r   = rh * 48 + (idx >> 4);
        int k4  = idx & 15;
        const float* base = (r < 32) ? Wq : ((r < 64) ? Wk : Wv);
        pw[t] = __ldg((const float4*)(base + (r & 31) * 256) + k4);
    }

    for (int kc = 0; kc < 4; ++kc) {
        __syncthreads();      // previous compute finished reading smem
        // commit prefetched chunk to smem
#pragma unroll
        for (int t = 0; t < 4; ++t) {
            int idx = tid + t * 256;
            int c   = idx >> 4;
            int nq  = idx & 15;
            *(float4*)&xs[c * 64 + nq * 4] = px[t];
        }
#pragma unroll
        for (int t = 0; t < 3; ++t) {
            int idx = tid + t * 256;
            int r   = idx >> 4;           // local row 0..47
            int k4  = idx & 15;
            ws[(k4 * 4 + 0) * WPAD + r] = pw[t].x;
            ws[(k4 * 4 + 1) * WPAD + r] = pw[t].y;
            ws[(k4 * 4 + 2) * WPAD + r] = pw[t].z;
            ws[(k4 * 4 + 3) * WPAD + r] = pw[t].w;
        }
        // prefetch next chunk (overlaps with compute below)
        if (kc < 3) {
            const int kb = (kc + 1) * 64;
#pragma unroll
            for (int t = 0; t < 4; ++t) {
                int idx = tid + t * 256;
                int c   = idx >> 4;
                int nq  = idx & 15;
                px[t] = __ldg((const float4*)(x + (b * 256 + kb + c) * NTOK + n0) + nq);
            }
#pragma unroll
            for (int t = 0; t < 3; ++t) {
                int idx = tid + t * 256;
                int r   = rh * 48 + (idx >> 4);
                int k4  = idx & 15;
                const float* base = (r < 32) ? Wq : ((r < 64) ? Wk : Wv);
                pw[t] = __ldg((const float4*)(base + (r & 31) * 256 + kb) + k4);
            }
        }
        __syncthreads();

#pragma unroll 8
        for (int k = 0; k < 64; ++k) {
            float2 xv = *(const float2*)&xs[k * 64 + ng * 2];
            ull x0 = splat2(xv.x);
            ull x1 = splat2(xv.y);
            const float* wr = &ws[k * WPAD + rg * 6];
            ull wa = *(const ull*)(wr + 0);
            ull wb = *(const ull*)(wr + 2);
            ull wc = *(const ull*)(wr + 4);
            FMA2(acc2[0][0], wa, x0, acc2[0][0]); FMA2(acc2[0][1], wa, x1, acc2[0][1]);
            FMA2(acc2[1][0], wb, x0, acc2[1][0]); FMA2(acc2[1][1], wb, x1, acc2[1][1]);
            FMA2(acc2[2][0], wc, x0, acc2[2][0]); FMA2(acc2[2][1], wc, x1, acc2[2][1]);
        }
    }

    // write f16 outputs
#pragma unroll
    for (int pr = 0; pr < 3; ++pr) {
#pragma unroll
        for (int sub = 0; sub < 2; ++sub) {
            int r = rh * 48 + rg * 6 + pr * 2 + sub;
            int p = r >> 5;          // 0=q,1=k,2=v
            int h = (r >> 3) & 3;
            int d = r & 7;
            const float* bias = (p == 0) ? bq : ((p == 1) ? bk : bv);
            float bval = __ldg(&bias[h * 8 + d]);
            int bh = b * 4 + h;
#pragma unroll
            for (int c = 0; c < 2; ++c) {
                int n = n0 + ng * 2 + c;
                float val = (sub ? hi2(acc2[pr][c]) : lo2(acc2[pr][c])) + bval;
                if (p == 0) {
                    g_Qh[(bh * NTOK + n) * 8 + d] = __float2half_rn(LOG2E * val);
                } else if (p == 1) {
                    g_Kh[(bh * NTOK + n) * 8 + d] = __float2half_rn(val);
                } else {
                    g_VT[(bh * 8 + d) * NTOK + n] = __float2half_rn(val);
                }
            }
        }
    }
}

// ============================================================================
// Kernel 2: warp-MMA (HMMA) attention, smem-staged Q/V slabs, f16-accum GEMM1.
// 256 CTAs x 256 threads (8 warps). CTA item = (bh, 128-m block).
//   GEMM1: S[16m x 16n] f16 = K_frag · Q_fragᵀ   (2x mma.m16n8k8, f16 accum
//          -> 4 f16x2 regs already in GEMM2 A-fragment layout, no cvt)
//   epi:   E = ex2(S) in-place on f16x2
//   GEMM2: O[16m x 8d] fp32 += E · V_frag          (1x mma.m16n8k16)
// ============================================================================
#define VPAD 520   // sVT row stride in halves (1040B: f4-aligned, bank-spread)

__global__ void __launch_bounds__(256) attn_kernel()
{
    __shared__ __align__(16) __half sQ[512 * 8];      // [token][d]  8 KB
    __shared__ __align__(16) __half sVT[8 * VPAD];    // [d][n+pad]  8.1 KB

    const int tid  = threadIdx.x;
    const int warp = tid >> 5;
    const int lane = tid & 31;
    const int bh   = blockIdx.x >> 5;        // 256 blocks: 32 m-blocks per bh
    const int mb   = blockIdx.x & 31;
    const int m0   = mb * 128 + warp * 16;
    const int g    = lane >> 2;              // fragment row group 0..7
    const int q4   = lane & 3;               // fragment quad col 0..3

    // A fragment: K tokens m0..m0+15, d 0..7 (row-major m16k8) — loaded once
    const __half* Kbase = g_Kh + (size_t)bh * NTOK * 8;
    const uint32_t aK0 = *(const uint32_t*)(Kbase + (m0 + g) * 8 + q4 * 2);
    const uint32_t aK1 = *(const uint32_t*)(Kbase + (m0 + g + 8) * 8 + q4 * 2);

    float o0 = 0.f, o1 = 0.f, o2 = 0.f, o3 = 0.f;
    float denA = 0.f, denB = 0.f;

    const int vd = tid >> 5;    // staging: row d for this warp
    const int vj = tid & 31;

    for (int ns = 0; ns < 8; ++ns) {
        __syncthreads();   // previous inner loop done with smem
        // stage Q slab: 512 tokens x 8 halves = 512 float4
        {
            const float4* Qs = (const float4*)(g_Qh + (size_t)bh * NTOK * 8 + ns * 512 * 8);
            ((float4*)sQ)[tid]       = Qs[tid];
            ((float4*)sQ)[tid + 256] = Qs[tid + 256];
        }
        // stage V slab: 8 rows x 512 halves (64 float4 per row)
        {
            const float4* Vs = (const float4*)(g_VT + (size_t)(bh * 8 + vd) * NTOK + ns * 512);
            float4* dst = (float4*)(sVT + vd * VPAD);
            dst[vj]      = Vs[vj];
            dst[vj + 32] = Vs[vj + 32];
        }
        __syncthreads();

#pragma unroll 4
        for (int p = 0; p < 32; ++p) {
            const int n0 = p * 16;
            // Q B-fragments (col-major k8 x n8)
            uint32_t bQ0 = *(const uint32_t*)(sQ + (n0 + g) * 8 + q4 * 2);
            uint32_t bQ1 = *(const uint32_t*)(sQ + (n0 + 8 + g) * 8 + q4 * 2);
            // V B-fragment (col-major k16 x n8): d = g
            uint32_t bV0 = *(const uint32_t*)(sVT + g * VPAD + n0 + q4 * 2);
            uint32_t bV1 = *(const uint32_t*)(sVT + g * VPAD + n0 + 8 + q4 * 2);

            // GEMM1 with f16 accumulators: outputs are the f16x2 S pairs
            // c0 = rows g (tile n), c1 = rows g+8 — exactly the GEMM2 A layout
            uint32_t e0, e1, e2, e3;
            asm volatile(
                "mma.sync.aligned.m16n8k8.row.col.f16.f16.f16.f16 "
                "{%0,%1}, {%2,%3}, {%4}, {%5,%6};"
                : "=r"(e0), "=r"(e1)
                : "r"(aK0), "r"(aK1), "r"(bQ0), "r"(0u), "r"(0u));
            asm volatile(
                "mma.sync.aligned.m16n8k8.row.col.f16.f16.f16.f16 "
                "{%0,%1}, {%2,%3}, {%4}, {%5,%6};"
                : "=r"(e2), "=r"(e3)
                : "r"(aK0), "r"(aK1), "r"(bQ1), "r"(0u), "r"(0u));

            // E = ex2(S) in place (MUFU f16x2: 2 exps per op)
            asm("ex2.approx.f16x2 %0, %1;" : "=r"(e0) : "r"(e0));
            asm("ex2.approx.f16x2 %0, %1;" : "=r"(e1) : "r"(e1));
            asm("ex2.approx.f16x2 %0, %1;" : "=r"(e2) : "r"(e2));
            asm("ex2.approx.f16x2 %0, %1;" : "=r"(e3) : "r"(e3));

            // den accumulation (fp32): row g from e0,e2; row g+8 from e1,e3
            {
                __half2 hA = __hadd2(*(__half2*)&e0, *(__half2*)&e2);
                __half2 hB = __hadd2(*(__half2*)&e1, *(__half2*)&e3);
                float2 fA = __half22float2(hA);
                float2 fB = __half22float2(hB);
                denA += fA.x + fA.y;
                denB += fB.x + fB.y;
            }

            asm volatile(
                "mma.sync.aligned.m16n8k16.row.col.f32.f16.f16.f32 "
                "{%0,%1,%2,%3}, {%4,%5,%6,%7}, {%8,%9}, {%0,%1,%2,%3};"
                : "+f"(o0), "+f"(o1), "+f"(o2), "+f"(o3)
                : "r"(e0), "r"(e1), "r"(e2), "r"(e3), "r"(bV0), "r"(bV1));
        }
    }

    // quad-reduce den over the 4 lanes sharing each row
    denA += __shfl_xor_sync(0xFFFFFFFFu, denA, 1);
    denA += __shfl_xor_sync(0xFFFFFFFFu, denA, 2);
    denB += __shfl_xor_sync(0xFFFFFFFFu, denB, 1);
    denB += __shfl_xor_sync(0xFFFFFFFFu, denB, 2);
    const float rA = 1.0f / denA;
    const float rB = 1.0f / denB;

    float* OpA = g_O + ((size_t)(bh * NTOK + m0 + g)) * 8 + q4 * 2;
    float* OpB = g_O + ((size_t)(bh * NTOK + m0 + g + 8)) * 8 + q4 * 2;
    *(float2*)OpA = make_float2(o0 * rA, o1 * rA);
    *(float2*)OpB = make_float2(o2 * rB, o3 * rB);
}

// ============================================================================
// Kernel 3: Wo projection + bias + gamma + residual.
// Thread per (bh, m, e-half): 65536 threads -> 256 blocks.
// ============================================================================
__global__ void __launch_bounds__(256) out_kernel(
    const float* __restrict__ x,
    const float* __restrict__ Wo, const float* __restrict__ bo,
    const float* __restrict__ gamma,
    float* __restrict__ out)
{
    __shared__ float wo_s[256];   // 32 e x 8 d
    __shared__ float bo_s[32];
    __shared__ float gam_s;

    const int t  = blockIdx.x * 256 + threadIdx.x;
    const int m  = t & 4095;
    const int bh = (t >> 12) & 7;
    const int eh = t >> 15;       // e-half (uniform per block)
    const int b  = bh >> 2;
    const int h  = bh & 3;

    wo_s[threadIdx.x] = Wo[h * 512 + eh * 256 + threadIdx.x];
    if (threadIdx.x < 32) bo_s[threadIdx.x] = bo[h * 64 + eh * 32 + threadIdx.x];
    if (threadIdx.x == 0) gam_s = gamma[h];
    __syncthreads();

    const float4* op = (const float4*)(g_O + (size_t)(bh * NTOK + m) * 8);
    float4 a = op[0], c = op[1];
    float o[8] = {a.x, a.y, a.z, a.w, c.x, c.y, c.z, c.w};

    const float gam = gam_s;
#pragma unroll 4
    for (int e = 0; e < 32; ++e) {
        float y = bo_s[e];
#pragma unroll
        for (int d = 0; d < 8; ++d) y += wo_s[e * 8 + d] * o[d];
        int idx = b * (256 * NTOK) + (h * 64 + eh * 32 + e) * NTOK + m;
        out[idx] = gam * y + x[idx];
    }
}

// ============================================================================
extern "C" void kernel_launch(void* const* d_in, const int* in_sizes, int n_in,
                              void* d_out, int out_size)
{
    const float* x     = (const float*)d_in[0];
    const float* Wq    = (const float*)d_in[1];
    const float* bq    = (const float*)d_in[2];
    const float* Wk    = (const float*)d_in[3];
    const float* bk    = (const float*)d_in[4];
    const float* Wv    = (const float*)d_in[5];
    const float* bv    = (const float*)d_in[6];
    const float* Wo    = (const float*)d_in[7];
    const float* bo    = (const float*)d_in[8];
    const float* gamma = (const float*)d_in[9];
    float* out = (float*)d_out;

    qkv_kernel<<<256, 256>>>(x, Wq, bq, Wk, bk, Wv, bv);
    attn_kernel<<<256, 256>>>();
    out_kernel<<<256, 256>>>(x, Wo, bo, gamma, out);
}

// round 13
// speedup vs baseline: 3.0794x; 1.0338x over previous
#include <cuda_runtime.h>
#include <cuda_fp16.h>
#include <cstdint>

typedef unsigned long long ull;

// ---------------- f32x2 packed math (PTX-only on sm_103a) ------------------
#define FMA2(d,a,b,c) asm("fma.rn.f32x2 %0, %1, %2, %3;" : "=l"(d) : "l"(a), "l"(b), "l"(c))

__device__ __forceinline__ ull splat2(float f) {
    unsigned u = __float_as_uint(f);
    return ((ull)u << 32) | (ull)u;
}
__device__ __forceinline__ float lo2(ull v) { return __uint_as_float((unsigned)v); }
__device__ __forceinline__ float hi2(ull v) { return __uint_as_float((unsigned)(v >> 32)); }

// ---------------- problem constants ----------------------------------------
// B=2, C=256, N=4096, NUM_HEAD=4, D=8, AT_HEAD=64, BH=8
#define NTOK   4096
#define BH_CNT 8
#define LOG2E  1.4426950408889634f

// ---------------- device scratch (no allocation allowed) -------------------
// gQh/gKh: f16 [bh][n][8]   (q pre-scaled by log2e)
// gVT:     f16 [bh][8][n]   (v transposed: d-major)
// gO:      fp32 [bh][m][8]  (normalized attention output)
__device__ __half g_Qh[BH_CNT * NTOK * 8];
__device__ __half g_Kh[BH_CNT * NTOK * 8];
__device__ __half g_VT[BH_CNT * 8 * NTOK];
__device__ float  g_O [BH_CNT * NTOK * 8];

// ============================================================================
// Kernel 1: fused QKV projection, FFMA2 row-pairs, software-pipelined chunks.
// (unchanged from R12 — proven at 22.3 us)
// ============================================================================
#define WPAD 52   // W smem row stride (floats)

__global__ void __launch_bounds__(256, 2) qkv_kernel(
    const float* __restrict__ x,
    const float* __restrict__ Wq, const float* __restrict__ bq,
    const float* __restrict__ Wk, const float* __restrict__ bk,
    const float* __restrict__ Wv, const float* __restrict__ bv)
{
    __shared__ __align__(16) float xs[64 * 64];     // [k_local][n]  16 KB
    __shared__ __align__(16) float ws[64 * WPAD];   // [k_local][r]  13.3 KB

    const int b   = blockIdx.x >> 7;            // 256 blocks
    const int rh  = (blockIdx.x >> 6) & 1;      // row half: rows rh*48 .. +47
    const int n0  = (blockIdx.x & 63) * 64;
    const int tid = threadIdx.x;
    const int rg  = tid >> 5;                   // warp: 6 rows each
    const int ng  = tid & 31;                   // 2 n each

    ull acc2[3][2];
#pragma unroll
    for (int pr = 0; pr < 3; ++pr) { acc2[pr][0] = 0ull; acc2[pr][1] = 0ull; }

    // prefetch registers (chunk 0)
    float4 px[4], pw[3];
#pragma unroll
    for (int t = 0; t < 4; ++t) {
        int idx = tid + t * 256;
        int c   = idx >> 4;
        int nq  = idx & 15;
        px[t] = __ldg((const float4*)(x + (b * 256 + c) * NTOK + n0) + nq);
    }
#pragma unroll
    for (int t = 0; t < 3; ++t) {
        int idx = tid + t * 256;
        int r   = rh * 48 + (idx >> 4);
        int k4  = idx & 15;
        const float* base = (r < 32) ? Wq : ((r < 64) ? Wk : Wv);
        pw[t] = __ldg((const float4*)(base + (r & 31) * 256) + k4);
    }

    for (int kc = 0; kc < 4; ++kc) {
        __syncthreads();      // previous compute finished reading smem
        // commit prefetched chunk to smem
#pragma unroll
        for (int t = 0; t < 4; ++t) {
            int idx = tid + t * 256;
            int c   = idx >> 4;
            int nq  = idx & 15;
            *(float4*)&xs[c * 64 + nq * 4] = px[t];
        }
#pragma unroll
        for (int t = 0; t < 3; ++t) {
            int idx = tid + t * 256;
            int r   = idx >> 4;           // local row 0..47
            int k4  = idx & 15;
            ws[(k4 * 4 + 0) * WPAD + r] = pw[t].x;
            ws[(k4 * 4 + 1) * WPAD + r] = pw[t].y;
            ws[(k4 * 4 + 2) * WPAD + r] = pw[t].z;
            ws[(k4 * 4 + 3) * WPAD + r] = pw[t].w;
        }
        // prefetch next chunk (overlaps with compute below)
        if (kc < 3) {
            const int kb = (kc + 1) * 64;
#pragma unroll
            for (int t = 0; t < 4; ++t) {
                int idx = tid + t * 256;
                int c   = idx >> 4;
                int nq  = idx & 15;
                px[t] = __ldg((const float4*)(x + (b * 256 + kb + c) * NTOK + n0) + nq);
            }
#pragma unroll
            for (int t = 0; t < 3; ++t) {
                int idx = tid + t * 256;
                int r   = rh * 48 + (idx >> 4);
                int k4  = idx & 15;
                const float* base = (r < 32) ? Wq : ((r < 64) ? Wk : Wv);
                pw[t] = __ldg((const float4*)(base + (r & 31) * 256 + kb) + k4);
            }
        }
        __syncthreads();

#pragma unroll 8
        for (int k = 0; k < 64; ++k) {
            float2 xv = *(const float2*)&xs[k * 64 + ng * 2];
            ull x0 = splat2(xv.x);
            ull x1 = splat2(xv.y);
            const float* wr = &ws[k * WPAD + rg * 6];
            ull wa = *(const ull*)(wr + 0);
            ull wb = *(const ull*)(wr + 2);
            ull wc = *(const ull*)(wr + 4);
            FMA2(acc2[0][0], wa, x0, acc2[0][0]); FMA2(acc2[0][1], wa, x1, acc2[0][1]);
            FMA2(acc2[1][0], wb, x0, acc2[1][0]); FMA2(acc2[1][1], wb, x1, acc2[1][1]);
            FMA2(acc2[2][0], wc, x0, acc2[2][0]); FMA2(acc2[2][1], wc, x1, acc2[2][1]);
        }
    }

    // write f16 outputs
#pragma unroll
    for (int pr = 0; pr < 3; ++pr) {
#pragma unroll
        for (int sub = 0; sub < 2; ++sub) {
            int r = rh * 48 + rg * 6 + pr * 2 + sub;
            int p = r >> 5;          // 0=q,1=k,2=v
            int h = (r >> 3) & 3;
            int d = r & 7;
            const float* bias = (p == 0) ? bq : ((p == 1) ? bk : bv);
            float bval = __ldg(&bias[h * 8 + d]);
            int bh = b * 4 + h;
#pragma unroll
            for (int c = 0; c < 2; ++c) {
                int n = n0 + ng * 2 + c;
                float val = (sub ? hi2(acc2[pr][c]) : lo2(acc2[pr][c])) + bval;
                if (p == 0) {
                    g_Qh[(bh * NTOK + n) * 8 + d] = __float2half_rn(LOG2E * val);
                } else if (p == 1) {
                    g_Kh[(bh * NTOK + n) * 8 + d] = __float2half_rn(val);
                } else {
                    g_VT[(bh * 8 + d) * NTOK + n] = __float2half_rn(val);
                }
            }
        }
    }
}

// ============================================================================
// Kernel 2: warp-MMA (HMMA) attention, smem-staged Q/V slabs, f16-accum GEMM1,
// and tensor-pipe denominator: GEMM2 extended with a constant ones-column
// B-fragment, so den accumulates in a second HMMA instead of ~10 scalar ops.
// 256 CTAs x 256 threads (8 warps). CTA item = (bh, 128-m block).
//   GEMM1: S[16m x 16n] f16 = K_frag · Q_fragᵀ   (2x mma.m16n8k8, f16 accum)
//   epi:   E = ex2(S) in-place on f16x2 (MUFU, 2 exps/op)
//   GEMM2a: O[16m x 8d]  fp32 += E · V_frag       (mma.m16n8k16)
//   GEMM2b: P[16m x 8]   fp32 += E · Ones_frag    (mma.m16n8k16, const B)
//           -> P col 0 = denominator (lanes q4==0 hold it)
// ============================================================================
#define VPAD 520   // sVT row stride in halves (1040B: f4-aligned, bank-spread)

__global__ void __launch_bounds__(256, 2) attn_kernel()
{
    __shared__ __align__(16) __half sQ[512 * 8];      // [token][d]  8 KB
    __shared__ __align__(16) __half sVT[8 * VPAD];    // [d][n+pad]  8.1 KB

    const int tid  = threadIdx.x;
    const int warp = tid >> 5;
    const int lane = tid & 31;
    const int bh   = blockIdx.x >> 5;        // 256 blocks: 32 m-blocks per bh
    const int mb   = blockIdx.x & 31;
    const int m0   = mb * 128 + warp * 16;
    const int g    = lane >> 2;              // fragment row group 0..7
    const int q4   = lane & 3;               // fragment quad col 0..3

    // A fragment: K tokens m0..m0+15, d 0..7 (row-major m16k8) — loaded once
    const __half* Kbase = g_Kh + (size_t)bh * NTOK * 8;
    const uint32_t aK0 = *(const uint32_t*)(Kbase + (m0 + g) * 8 + q4 * 2);
    const uint32_t aK1 = *(const uint32_t*)(Kbase + (m0 + g + 8) * 8 + q4 * 2);

    // constant ones B-fragment for the den GEMM: col 0 of the extension is 1,
    // cols 1..7 are 0. B col-major k16n8: lane holds (k=q4*2{,+1}, n=g) and
    // (k=q4*2+8{,+1}, n=g) -> halves (1,1) when g==0, else 0.
    const uint32_t bOnes = (g == 0) ? 0x3C003C00u : 0u;

    float o0 = 0.f, o1 = 0.f, o2 = 0.f, o3 = 0.f;   // E·V accum
    float p0 = 0.f, p1 = 0.f, p2 = 0.f, p3 = 0.f;   // den accum (col 0 used)

    const int vd = tid >> 5;    // staging: row d for this warp
    const int vj = tid & 31;

    for (int ns = 0; ns < 8; ++ns) {
        __syncthreads();   // previous inner loop done with smem
        // stage Q slab: 512 tokens x 8 halves = 512 float4
        {
            const float4* Qs = (const float4*)(g_Qh + (size_t)bh * NTOK * 8 + ns * 512 * 8);
            ((float4*)sQ)[tid]       = Qs[tid];
            ((float4*)sQ)[tid + 256] = Qs[tid + 256];
        }
        // stage V slab: 8 rows x 512 halves (64 float4 per row)
        {
            const float4* Vs = (const float4*)(g_VT + (size_t)(bh * 8 + vd) * NTOK + ns * 512);
            float4* dst = (float4*)(sVT + vd * VPAD);
            dst[vj]      = Vs[vj];
            dst[vj + 32] = Vs[vj + 32];
        }
        __syncthreads();

#pragma unroll 4
        for (int p = 0; p < 32; ++p) {
            const int n0 = p * 16;
            // Q B-fragments (col-major k8 x n8)
            uint32_t bQ0 = *(const uint32_t*)(sQ + (n0 + g) * 8 + q4 * 2);
            uint32_t bQ1 = *(const uint32_t*)(sQ + (n0 + 8 + g) * 8 + q4 * 2);
            // V B-fragment (col-major k16 x n8): d = g
            uint32_t bV0 = *(const uint32_t*)(sVT + g * VPAD + n0 + q4 * 2);
            uint32_t bV1 = *(const uint32_t*)(sVT + g * VPAD + n0 + 8 + q4 * 2);

            // GEMM1 with f16 accumulators -> f16x2 S pairs (GEMM2 A layout)
            uint32_t e0, e1, e2, e3;
            asm volatile(
                "mma.sync.aligned.m16n8k8.row.col.f16.f16.f16.f16 "
                "{%0,%1}, {%2,%3}, {%4}, {%5,%6};"
                : "=r"(e0), "=r"(e1)
                : "r"(aK0), "r"(aK1), "r"(bQ0), "r"(0u), "r"(0u));
            asm volatile(
                "mma.sync.aligned.m16n8k8.row.col.f16.f16.f16.f16 "
                "{%0,%1}, {%2,%3}, {%4}, {%5,%6};"
                : "=r"(e2), "=r"(e3)
                : "r"(aK0), "r"(aK1), "r"(bQ1), "r"(0u), "r"(0u));

            // E = ex2(S) in place (MUFU f16x2: 2 exps per op)
            asm("ex2.approx.f16x2 %0, %1;" : "=r"(e0) : "r"(e0));
            asm("ex2.approx.f16x2 %0, %1;" : "=r"(e1) : "r"(e1));
            asm("ex2.approx.f16x2 %0, %1;" : "=r"(e2) : "r"(e2));
            asm("ex2.approx.f16x2 %0, %1;" : "=r"(e3) : "r"(e3));

            // GEMM2a: O += E · V
            asm volatile(
                "mma.sync.aligned.m16n8k16.row.col.f32.f16.f16.f32 "
                "{%0,%1,%2,%3}, {%4,%5,%6,%7}, {%8,%9}, {%0,%1,%2,%3};"
                : "+f"(o0), "+f"(o1), "+f"(o2), "+f"(o3)
                : "r"(e0), "r"(e1), "r"(e2), "r"(e3), "r"(bV0), "r"(bV1));
            // GEMM2b: P += E · Ones  (den lands in col 0 -> lanes q4==0)
            asm volatile(
                "mma.sync.aligned.m16n8k16.row.col.f32.f16.f16.f32 "
                "{%0,%1,%2,%3}, {%4,%5,%6,%7}, {%8,%9}, {%0,%1,%2,%3};"
                : "+f"(p0), "+f"(p1), "+f"(p2), "+f"(p3)
                : "r"(e0), "r"(e1), "r"(e2), "r"(e3), "r"(bOnes), "r"(bOnes));
        }
    }

    // den lives in p0 (row g) / p2 (row g+8) of lanes with q4==0; broadcast
    const float denA = __shfl_sync(0xFFFFFFFFu, p0, g * 4);
    const float denB = __shfl_sync(0xFFFFFFFFu, p2, g * 4);
    (void)p1; (void)p3;
    const float rA = 1.0f / denA;
    const float rB = 1.0f / denB;

    float* OpA = g_O + ((size_t)(bh * NTOK + m0 + g)) * 8 + q4 * 2;
    float* OpB = g_O + ((size_t)(bh * NTOK + m0 + g + 8)) * 8 + q4 * 2;
    *(float2*)OpA = make_float2(o0 * rA, o1 * rA);
    *(float2*)OpB = make_float2(o2 * rB, o3 * rB);
}

// ============================================================================
// Kernel 3: Wo projection + bias + gamma + residual.
// Thread per (bh, m, e-half): 65536 threads -> 256 blocks.
// ============================================================================
__global__ void __launch_bounds__(256) out_kernel(
    const float* __restrict__ x,
    const float* __restrict__ Wo, const float* __restrict__ bo,
    const float* __restrict__ gamma,
    float* __restrict__ out)
{
    __shared__ float wo_s[256];   // 32 e x 8 d
    __shared__ float bo_s[32];
    __shared__ float gam_s;

    const int t  = blockIdx.x * 256 + threadIdx.x;
    const int m  = t & 4095;
    const int bh = (t >> 12) & 7;
    const int eh = t >> 15;       // e-half (uniform per block)
    const int b  = bh >> 2;
    const int h  = bh & 3;

    wo_s[threadIdx.x] = Wo[h * 512 + eh * 256 + threadIdx.x];
    if (threadIdx.x < 32) bo_s[threadIdx.x] = bo[h * 64 + eh * 32 + threadIdx.x];
    if (threadIdx.x == 0) gam_s = gamma[h];
    __syncthreads();

    const float4* op = (const float4*)(g_O + (size_t)(bh * NTOK + m) * 8);
    float4 a = op[0], c = op[1];
    float o[8] = {a.x, a.y, a.z, a.w, c.x, c.y, c.z, c.w};

    const float gam = gam_s;
#pragma unroll 4
    for (int e = 0; e < 32; ++e) {
        float y = bo_s[e];
#pragma unroll
        for (int d = 0; d < 8; ++d) y += wo_s[e * 8 + d] * o[d];
        int idx = b * (256 * NTOK) + (h * 64 + eh * 32 + e) * NTOK + m;
        out[idx] = gam * y + x[idx];
    }
}

// ============================================================================
extern "C" void kernel_launch(void* const* d_in, const int* in_sizes, int n_in,
                              void* d_out, int out_size)
{
    const float* x     = (const float*)d_in[0];
    const float* Wq    = (const float*)d_in[1];
    const float* bq    = (const float*)d_in[2];
    const float* Wk    = (const float*)d_in[3];
    const float* bk    = (const float*)d_in[4];
    const float* Wv    = (const float*)d_in[5];
    const float* bv    = (const float*)d_in[6];
    const float* Wo    = (const float*)d_in[7];
    const float* bo    = (const float*)d_in[8];
    const float* gamma = (const float*)d_in[9];
    float* out = (float*)d_out;

    qkv_kernel<<<256, 256>>>(x, Wq, bq, Wk, bk, Wv, bv);
    attn_kernel<<<256, 256>>>();
    out_kernel<<<256, 256>>>(x, Wo, bo, gamma, out);
}

// round 14
// speedup vs baseline: 3.8003x; 1.2341x over previous
#include <cuda_runtime.h>
#include <cuda_fp16.h>
#include <cstdint>

// ---------------- problem constants ----------------------------------------
// B=2, C=256, N=4096, NUM_HEAD=4, D=8, AT_HEAD=64, BH=8
#define NTOK   4096
#define BH_CNT 8
#define LOG2E  1.4426950408889634f

// ---------------- device scratch (no allocation allowed) -------------------
// gQh/gKh: f16 [bh][n][8]   (q pre-scaled by log2e)
// gVT:     f16 [bh][8][n]   (v transposed: d-major)
// gO:      fp32 [bh][m][8]  (normalized attention output)
__device__ __half g_Qh[BH_CNT * NTOK * 8];
__device__ __half g_Kh[BH_CNT * NTOK * 8];
__device__ __half g_VT[BH_CNT * 8 * NTOK];
__device__ float  g_O [BH_CNT * NTOK * 8];

// ============================================================================
// Kernel 1: HMMA QKV projection. C^T[n][96] = X^T[n][256] · W^T[256][96].
// 256 CTAs = b(2) x n-tile(128 of 32 tokens). 256 threads (8 warps):
//   warp -> m-tile mt = warp&1 (16 tokens), n8-tiles nh*3..nh*3+2 (nh=warp>>1).
// A: x^T f16 smem tile [32 n][256 c] (pad 264: conflict-free LDS.32 frags).
// B: W k-paired uint32 smem [k2][96] stride 104 (conflict-free LDS.32 frags).
// mma.m16n8k8.f32: out rows = tokens, cols = the 96 qkv channels -> direct
// stores into g_Qh/g_Kh [n][8] and g_VT [d][n].
// ============================================================================
#define XS_STRIDE 264   // halves per xs row

__global__ void __launch_bounds__(256, 2) qkv_kernel(
    const float* __restrict__ x,
    const float* __restrict__ Wq, const float* __restrict__ bq,
    const float* __restrict__ Wk, const float* __restrict__ bk,
    const float* __restrict__ Wv, const float* __restrict__ bv)
{
    __shared__ __align__(16) __half    xs[32 * XS_STRIDE];  // 16.9 KB
    __shared__ __align__(16) uint32_t  ws32[32 * 104];      // 13.3 KB
    __shared__ float bias_s[96];

    const int b    = blockIdx.x >> 7;
    const int n0   = (blockIdx.x & 127) * 32;
    const int tid  = threadIdx.x;
    const int warp = tid >> 5;
    const int lane = tid & 31;
    const int g    = lane >> 2;          // fragment row group 0..7
    const int q4   = lane & 3;           // fragment quad 0..3
    const int mt   = warp & 1;           // token m-tile (16 tokens)
    const int nh   = warp >> 1;          // output n8-tile group (3 tiles)

    if (tid < 96) {
        float bv_;
        if (tid < 32)      bv_ = __ldg(&bq[tid]);
        else if (tid < 64) bv_ = __ldg(&bk[tid - 32]);
        else               bv_ = __ldg(&bv[tid - 64]);
        bias_s[tid] = bv_;
    }

    // stage x^T tile: f16 [n][c]; coalesced LDG.32 over n, pack c-pairs
    {
        const int sn = lane;         // token within tile
        const int sg = warp;         // c-group of 32
        const float* xb = x + (size_t)(b * 256 + sg * 32) * NTOK + n0 + sn;
#pragma unroll
        for (int c2 = 0; c2 < 16; ++c2) {
            float f0 = __ldg(xb + (2 * c2)     * NTOK);
            float f1 = __ldg(xb + (2 * c2 + 1) * NTOK);
            __half2 h2 = __floats2half2_rn(f0, f1);
            *(__half2*)&xs[sn * XS_STRIDE + sg * 32 + 2 * c2] = h2;
        }
    }

    float acc[3][4];
#pragma unroll
    for (int j = 0; j < 3; ++j)
#pragma unroll
        for (int i = 0; i < 4; ++i) acc[j][i] = 0.0f;

    for (int kc = 0; kc < 4; ++kc) {
        __syncthreads();
        // stage W chunk: ws32[k2][r] = half2(W[r][kc*64+2k2], W[r][kc*64+2k2+1])
#pragma unroll
        for (int t = 0; t < 6; ++t) {
            int idx = tid + t * 256;
            int r   = idx >> 4;
            int kq  = idx & 15;
            const float* base = (r < 32) ? Wq : ((r < 64) ? Wk : Wv);
            float4 w = __ldg((const float4*)(base + (r & 31) * 256 + kc * 64) + kq);
            __half2 h0 = __floats2half2_rn(w.x, w.y);
            __half2 h1 = __floats2half2_rn(w.z, w.w);
            ws32[(kq * 2)     * 104 + r] = *(uint32_t*)&h0;
            ws32[(kq * 2 + 1) * 104 + r] = *(uint32_t*)&h1;
        }
        __syncthreads();

#pragma unroll
        for (int k8 = 0; k8 < 8; ++k8) {
            const int cbase = kc * 64 + k8 * 8 + 2 * q4;
            uint32_t a0 = *(const uint32_t*)&xs[(mt * 16 + g)     * XS_STRIDE + cbase];
            uint32_t a1 = *(const uint32_t*)&xs[(mt * 16 + g + 8) * XS_STRIDE + cbase];
            const uint32_t* wrow = &ws32[(k8 * 4 + q4) * 104];
#pragma unroll
            for (int j = 0; j < 3; ++j) {
                uint32_t bf = wrow[(nh * 3 + j) * 8 + g];
                asm volatile(
                    "mma.sync.aligned.m16n8k8.row.col.f32.f16.f16.f32 "
                    "{%0,%1,%2,%3}, {%4,%5}, {%6}, {%0,%1,%2,%3};"
                    : "+f"(acc[j][0]), "+f"(acc[j][1]), "+f"(acc[j][2]), "+f"(acc[j][3])
                    : "r"(a0), "r"(a1), "r"(bf));
            }
        }
    }

    // epilogue: bias (+log2e for q), write to attention layouts
    const int nA = n0 + mt * 16 + g;     // token rows g, g+8
    const int nB = nA + 8;
#pragma unroll
    for (int j = 0; j < 3; ++j) {
        int tile = nh * 3 + j;
        int p = tile >> 2;               // 0=q (tiles 0-3), 1=k (4-7), 2=v (8-11)
        int h = tile & 3;
        int d = 2 * q4;
        int bh = b * 4 + h;
        float b0 = bias_s[tile * 8 + d];
        float b1 = bias_s[tile * 8 + d + 1];
        float v00 = acc[j][0] + b0, v01 = acc[j][1] + b1;
        float v10 = acc[j][2] + b0, v11 = acc[j][3] + b1;
        if (p == 0) {
            v00 *= LOG2E; v01 *= LOG2E; v10 *= LOG2E; v11 *= LOG2E;
            *(__half2*)&g_Qh[((size_t)bh * NTOK + nA) * 8 + d] = __floats2half2_rn(v00, v01);
            *(__half2*)&g_Qh[((size_t)bh * NTOK + nB) * 8 + d] = __floats2half2_rn(v10, v11);
        } else if (p == 1) {
            *(__half2*)&g_Kh[((size_t)bh * NTOK + nA) * 8 + d] = __floats2half2_rn(v00, v01);
            *(__half2*)&g_Kh[((size_t)bh * NTOK + nB) * 8 + d] = __floats2half2_rn(v10, v11);
        } else {
            __half* vt0 = g_VT + ((size_t)bh * 8 + d)     * NTOK;
            __half* vt1 = g_VT + ((size_t)bh * 8 + d + 1) * NTOK;
            vt0[nA] = __float2half_rn(v00);
            vt1[nA] = __float2half_rn(v01);
            vt0[nB] = __float2half_rn(v10);
            vt1[nB] = __float2half_rn(v11);
        }
    }
}

// ============================================================================
// Kernel 2: warp-MMA (HMMA) attention, smem-staged Q/V slabs, f16-accum GEMM1,
// tensor-pipe denominator (ones-column GEMM2b). Unchanged from R13 (proven).
// ============================================================================
#define VPAD 520   // sVT row stride in halves (1040B: f4-aligned, bank-spread)

__global__ void __launch_bounds__(256, 2) attn_kernel()
{
    __shared__ __align__(16) __half sQ[512 * 8];      // [token][d]  8 KB
    __shared__ __align__(16) __half sVT[8 * VPAD];    // [d][n+pad]  8.1 KB

    const int tid  = threadIdx.x;
    const int warp = tid >> 5;
    const int lane = tid & 31;
    const int bh   = blockIdx.x >> 5;        // 256 blocks: 32 m-blocks per bh
    const int mb   = blockIdx.x & 31;
    const int m0   = mb * 128 + warp * 16;
    const int g    = lane >> 2;              // fragment row group 0..7
    const int q4   = lane & 3;               // fragment quad col 0..3

    // A fragment: K tokens m0..m0+15, d 0..7 (row-major m16k8) — loaded once
    const __half* Kbase = g_Kh + (size_t)bh * NTOK * 8;
    const uint32_t aK0 = *(const uint32_t*)(Kbase + (m0 + g) * 8 + q4 * 2);
    const uint32_t aK1 = *(const uint32_t*)(Kbase + (m0 + g + 8) * 8 + q4 * 2);

    // constant ones B-fragment for the den GEMM (col 0 = 1, cols 1..7 = 0)
    const uint32_t bOnes = (g == 0) ? 0x3C003C00u : 0u;

    float o0 = 0.f, o1 = 0.f, o2 = 0.f, o3 = 0.f;   // E·V accum
    float p0 = 0.f, p1 = 0.f, p2 = 0.f, p3 = 0.f;   // den accum (col 0 used)

    const int vd = tid >> 5;    // staging: row d for this warp
    const int vj = tid & 31;

    for (int ns = 0; ns < 8; ++ns) {
        __syncthreads();   // previous inner loop done with smem
        // stage Q slab: 512 tokens x 8 halves = 512 float4
        {
            const float4* Qs = (const float4*)(g_Qh + (size_t)bh * NTOK * 8 + ns * 512 * 8);
            ((float4*)sQ)[tid]       = Qs[tid];
            ((float4*)sQ)[tid + 256] = Qs[tid + 256];
        }
        // stage V slab: 8 rows x 512 halves (64 float4 per row)
        {
            const float4* Vs = (const float4*)(g_VT + (size_t)(bh * 8 + vd) * NTOK + ns * 512);
            float4* dst = (float4*)(sVT + vd * VPAD);
            dst[vj]      = Vs[vj];
            dst[vj + 32] = Vs[vj + 32];
        }
        __syncthreads();

#pragma unroll 4
        for (int p = 0; p < 32; ++p) {
            const int n0 = p * 16;
            uint32_t bQ0 = *(const uint32_t*)(sQ + (n0 + g) * 8 + q4 * 2);
            uint32_t bQ1 = *(const uint32_t*)(sQ + (n0 + 8 + g) * 8 + q4 * 2);
            uint32_t bV0 = *(const uint32_t*)(sVT + g * VPAD + n0 + q4 * 2);
            uint32_t bV1 = *(const uint32_t*)(sVT + g * VPAD + n0 + 8 + q4 * 2);

            // GEMM1 with f16 accumulators -> f16x2 S pairs (GEMM2 A layout)
            uint32_t e0, e1, e2, e3;
            asm volatile(
                "mma.sync.aligned.m16n8k8.row.col.f16.f16.f16.f16 "
                "{%0,%1}, {%2,%3}, {%4}, {%5,%6};"
                : "=r"(e0), "=r"(e1)
                : "r"(aK0), "r"(aK1), "r"(bQ0), "r"(0u), "r"(0u));
            asm volatile(
                "mma.sync.aligned.m16n8k8.row.col.f16.f16.f16.f16 "
                "{%0,%1}, {%2,%3}, {%4}, {%5,%6};"
                : "=r"(e2), "=r"(e3)
                : "r"(aK0), "r"(aK1), "r"(bQ1), "r"(0u), "r"(0u));

            // E = ex2(S) in place (MUFU f16x2: 2 exps per op)
            asm("ex2.approx.f16x2 %0, %1;" : "=r"(e0) : "r"(e0));
            asm("ex2.approx.f16x2 %0, %1;" : "=r"(e1) : "r"(e1));
            asm("ex2.approx.f16x2 %0, %1;" : "=r"(e2) : "r"(e2));
            asm("ex2.approx.f16x2 %0, %1;" : "=r"(e3) : "r"(e3));

            // GEMM2a: O += E · V
            asm volatile(
                "mma.sync.aligned.m16n8k16.row.col.f32.f16.f16.f32 "
                "{%0,%1,%2,%3}, {%4,%5,%6,%7}, {%8,%9}, {%0,%1,%2,%3};"
                : "+f"(o0), "+f"(o1), "+f"(o2), "+f"(o3)
                : "r"(e0), "r"(e1), "r"(e2), "r"(e3), "r"(bV0), "r"(bV1));
            // GEMM2b: P += E · Ones  (den lands in col 0)
            asm volatile(
                "mma.sync.aligned.m16n8k16.row.col.f32.f16.f16.f32 "
                "{%0,%1,%2,%3}, {%4,%5,%6,%7}, {%8,%9}, {%0,%1,%2,%3};"
                : "+f"(p0), "+f"(p1), "+f"(p2), "+f"(p3)
                : "r"(e0), "r"(e1), "r"(e2), "r"(e3), "r"(bOnes), "r"(bOnes));
        }
    }

    // den lives in p0 (row g) / p2 (row g+8) of lanes with q4==0; broadcast
    const float denA = __shfl_sync(0xFFFFFFFFu, p0, g * 4);
    const float denB = __shfl_sync(0xFFFFFFFFu, p2, g * 4);
    (void)p1; (void)p3;
    const float rA = 1.0f / denA;
    const float rB = 1.0f / denB;

    float* OpA = g_O + ((size_t)(bh * NTOK + m0 + g)) * 8 + q4 * 2;
    float* OpB = g_O + ((size_t)(bh * NTOK + m0 + g + 8)) * 8 + q4 * 2;
    *(float2*)OpA = make_float2(o0 * rA, o1 * rA);
    *(float2*)OpB = make_float2(o2 * rB, o3 * rB);
}

// ============================================================================
// Kernel 3: Wo projection + bias + gamma + residual. (unchanged)
// ============================================================================
__global__ void __launch_bounds__(256) out_kernel(
    const float* __restrict__ x,
    const float* __restrict__ Wo, const float* __restrict__ bo,
    const float* __restrict__ gamma,
    float* __restrict__ out)
{
    __shared__ float wo_s[256];   // 32 e x 8 d
    __shared__ float bo_s[32];
    __shared__ float gam_s;

    const int t  = blockIdx.x * 256 + threadIdx.x;
    const int m  = t & 4095;
    const int bh = (t >> 12) & 7;
    const int eh = t >> 15;       // e-half (uniform per block)
    const int b  = bh >> 2;
    const int h  = bh & 3;

    wo_s[threadIdx.x] = Wo[h * 512 + eh * 256 + threadIdx.x];
    if (threadIdx.x < 32) bo_s[threadIdx.x] = bo[h * 64 + eh * 32 + threadIdx.x];
    if (threadIdx.x == 0) gam_s = gamma[h];
    __syncthreads();

    const float4* op = (const float4*)(g_O + (size_t)(bh * NTOK + m) * 8);
    float4 a = op[0], c = op[1];
    float o[8] = {a.x, a.y, a.z, a.w, c.x, c.y, c.z, c.w};

    const float gam = gam_s;
#pragma unroll 4
    for (int e = 0; e < 32; ++e) {
        float y = bo_s[e];
#pragma unroll
        for (int d = 0; d < 8; ++d) y += wo_s[e * 8 + d] * o[d];
        int idx = b * (256 * NTOK) + (h * 64 + eh * 32 + e) * NTOK + m;
        out[idx] = gam * y + x[idx];
    }
}

// ============================================================================
extern "C" void kernel_launch(void* const* d_in, const int* in_sizes, int n_in,
                              void* d_out, int out_size)
{
    const float* x     = (const float*)d_in[0];
    const float* Wq    = (const float*)d_in[1];
    const float* bq    = (const float*)d_in[2];
    const float* Wk    = (const float*)d_in[3];
    const float* bk    = (const float*)d_in[4];
    const float* Wv    = (const float*)d_in[5];
    const float* bv    = (const float*)d_in[6];
    const float* Wo    = (const float*)d_in[7];
    const float* bo    = (const float*)d_in[8];
    const float* gamma = (const float*)d_in[9];
    float* out = (float*)d_out;

    qkv_kernel<<<256, 256>>>(x, Wq, bq, Wk, bk, Wv, bv);
    attn_kernel<<<256, 256>>>();
    out_kernel<<<256, 256>>>(x, Wo, bo, gamma, out);
}